// round 12
// baseline (speedup 1.0000x reference)
#include <cuda_runtime.h>
#include <cuda_bf16.h>
#include <cstdint>
#include <math.h>

#define BATCH 2
#define SEQ   2048
#define DIM   4096
#define NH    32
#define NKV   8
#define HD    128
#define NREP  4
#define MTOT  (BATCH*SEQ)   // 4096
#define NQ    (NH*HD)       // 4096
#define NKVD  (NKV*HD)      // 1024
#define NQKV  (NQ + 2*NKVD) // 6144

// -------- scratch (device globals) --------
__device__ __nv_bfloat16 g_xh[(size_t)MTOT*DIM],   g_xl[(size_t)MTOT*DIM];
__device__ __nv_bfloat16 g_wqkvTh[(size_t)NQKV*DIM], g_wqkvTl[(size_t)NQKV*DIM];
__device__ __nv_bfloat16 g_woTh[(size_t)DIM*NQ],   g_woTl[(size_t)DIM*NQ];
__device__ __nv_bfloat16 g_aoh[(size_t)MTOT*NQ],   g_aol[(size_t)MTOT*NQ];
__device__ __nv_bfloat16 g_qh[(size_t)MTOT*NQ],    g_ql[(size_t)MTOT*NQ];
__device__ __nv_bfloat16 g_kh[(size_t)MTOT*NKVD],  g_kl[(size_t)MTOT*NKVD];
__device__ __nv_bfloat16 g_vh[(size_t)MTOT*NKVD],  g_vl[(size_t)MTOT*NKVD];

// ============================================================
// PTX helpers
// ============================================================
__device__ __forceinline__ uint32_t smem_u32(const void* p) {
    uint32_t a;
    asm("{ .reg .u64 t; cvta.to.shared.u64 t, %1; cvt.u32.u64 %0, t; }" : "=r"(a) : "l"(p));
    return a;
}
__device__ __forceinline__ void cp16(uint32_t dst, const void* src) {
    asm volatile("cp.async.cg.shared.global [%0], [%1], 16;" :: "r"(dst), "l"(src));
}
#define CP_COMMIT()  asm volatile("cp.async.commit_group;")
#define CP_WAIT1()   asm volatile("cp.async.wait_group 1;")
#define CP_WAIT0()   asm volatile("cp.async.wait_group 0;")

__device__ __forceinline__ void ldsm4(uint32_t* r, uint32_t addr) {
    asm volatile("ldmatrix.sync.aligned.m8n8.x4.shared.b16 {%0,%1,%2,%3}, [%4];"
        : "=r"(r[0]), "=r"(r[1]), "=r"(r[2]), "=r"(r[3]) : "r"(addr));
}
__device__ __forceinline__ void ldsm4t(uint32_t* r, uint32_t addr) {
    asm volatile("ldmatrix.sync.aligned.m8n8.x4.trans.shared.b16 {%0,%1,%2,%3}, [%4];"
        : "=r"(r[0]), "=r"(r[1]), "=r"(r[2]), "=r"(r[3]) : "r"(addr));
}
__device__ __forceinline__ void mma16816(float* c, const uint32_t* a, const uint32_t* b) {
    asm volatile("mma.sync.aligned.m16n8k16.row.col.f32.bf16.bf16.f32 "
        "{%0,%1,%2,%3}, {%4,%5,%6,%7}, {%8,%9}, {%0,%1,%2,%3};"
        : "+f"(c[0]), "+f"(c[1]), "+f"(c[2]), "+f"(c[3])
        : "r"(a[0]), "r"(a[1]), "r"(a[2]), "r"(a[3]), "r"(b[0]), "r"(b[1]));
}
__device__ __forceinline__ uint32_t packbf(float a, float b) {
    __nv_bfloat162 v = __floats2bfloat162_rn(a, b);
    return *(uint32_t*)&v;
}

__device__ __forceinline__ uint32_t swz(int row, int seg) {     // 64B rows, 4 segs
    return (uint32_t)row * 64u + ((uint32_t)(seg ^ ((row >> 1) & 3)) << 4);
}
__device__ __forceinline__ uint32_t sw256(int row, int boff) {
    return (uint32_t)row * 256u + (uint32_t)(boff ^ ((row & 7) << 4));
}

// ============================================================
// GEMM mainloop shared structure: CTA 128x128, BK=32, 512 threads
// (16 warps 4x4), warp tile 32x32, 3-stage cp.async ring, ONE
// barrier per chunk.
// ============================================================
#define BM 128
#define BN 128
#define BK 32
#define GOFF_AH 0u
#define GOFF_AL 8192u
#define GOFF_BH 16384u
#define GOFF_BL 24576u
#define GSTAGE  32768u
#define GEMM_SMEM (3*32768)

#define GEMM_MAINLOOP(Ah, Al, Bh, Bl, Kdim)                                     \
    extern __shared__ char smem[];                                              \
    const uint32_t sb = smem_u32(smem);                                         \
    const int t = threadIdx.x;                                                  \
    const int lane = t & 31, wid = t >> 5;                                      \
    const int m0 = blockIdx.y * BM, n0 = blockIdx.x * BN;                       \
    const int lrow = t >> 2, lseg = t & 3;                                      \
    const __nv_bfloat16* gAh = (Ah) + (size_t)(m0 + lrow) * (Kdim) + lseg * 8;  \
    const __nv_bfloat16* gAl = (Al) + (size_t)(m0 + lrow) * (Kdim) + lseg * 8;  \
    const __nv_bfloat16* gBh = (Bh) + (size_t)(n0 + lrow) * (Kdim) + lseg * 8;  \
    const __nv_bfloat16* gBl = (Bl) + (size_t)(n0 + lrow) * (Kdim) + lseg * 8;  \
    const uint32_t loff = swz(lrow, lseg);                                      \
    const int wm = (wid & 3) * 32;                                              \
    const int wn = (wid >> 2) * 32;                                             \
    const int arow = wm + (lane & 7) + ((lane >> 3) & 1) * 8;                   \
    const int aseg = lane >> 4;                                                 \
    const int brow = wn + (lane & 7) + ((lane >> 4) & 1) * 8;                   \
    const int bseg = (lane >> 3) & 1;                                           \
    float acc[2][4][4];                                                         \
    _Pragma("unroll")                                                           \
    for (int i = 0; i < 2; i++)                                                 \
        _Pragma("unroll")                                                       \
        for (int j = 0; j < 4; j++)                                             \
            _Pragma("unroll")                                                   \
            for (int v = 0; v < 4; v++) acc[i][j][v] = 0.f;                     \
    const int nch = (Kdim) / BK;                                                \
    {                                                                           \
        uint32_t b0 = sb;                                                       \
        cp16(b0 + GOFF_AH + loff, gAh); cp16(b0 + GOFF_AL + loff, gAl);         \
        cp16(b0 + GOFF_BH + loff, gBh); cp16(b0 + GOFF_BL + loff, gBl);         \
        CP_COMMIT();                                                            \
        uint32_t b1 = sb + GSTAGE;                                              \
        cp16(b1 + GOFF_AH + loff, gAh + BK); cp16(b1 + GOFF_AL + loff, gAl + BK);\
        cp16(b1 + GOFF_BH + loff, gBh + BK); cp16(b1 + GOFF_BL + loff, gBl + BK);\
        CP_COMMIT();                                                            \
    }                                                                           \
    for (int ch = 0; ch < nch; ch++) {                                          \
        CP_WAIT1();                                                             \
        __syncthreads();                                                        \
        const uint32_t base = sb + (uint32_t)(ch % 3) * GSTAGE;                 \
        if (ch + 2 < nch) {                                                     \
            const uint32_t pb = sb + (uint32_t)((ch + 2) % 3) * GSTAGE;         \
            int k0 = (ch + 2) * BK;                                             \
            cp16(pb + GOFF_AH + loff, gAh + k0); cp16(pb + GOFF_AL + loff, gAl + k0);\
            cp16(pb + GOFF_BH + loff, gBh + k0); cp16(pb + GOFF_BL + loff, gBl + k0);\
        }                                                                       \
        CP_COMMIT();                                                            \
        _Pragma("unroll")                                                       \
        for (int ks = 0; ks < 2; ks++) {                                        \
            uint32_t ah[2][4], al[2][4], bh[2][4], bl[2][4];                    \
            _Pragma("unroll")                                                   \
            for (int mt = 0; mt < 2; mt++) {                                    \
                uint32_t off = swz(arow + mt * 16, ks * 2 + aseg);              \
                ldsm4(ah[mt], base + GOFF_AH + off);                            \
                ldsm4(al[mt], base + GOFF_AL + off);                            \
            }                                                                   \
            _Pragma("unroll")                                                   \
            for (int np = 0; np < 2; np++) {                                    \
                uint32_t off = swz(brow + np * 16, ks * 2 + bseg);              \
                ldsm4(bh[np], base + GOFF_BH + off);                            \
                ldsm4(bl[np], base + GOFF_BL + off);                            \
            }                                                                   \
            _Pragma("unroll")                                                   \
            for (int np = 0; np < 2; np++)                                      \
                _Pragma("unroll")                                               \
                for (int mt = 0; mt < 2; mt++) {                                \
                    mma16816(acc[mt][np * 2],     ah[mt], bh[np] + 0);          \
                    mma16816(acc[mt][np * 2],     ah[mt], bl[np] + 0);          \
                    mma16816(acc[mt][np * 2],     al[mt], bh[np] + 0);          \
                    mma16816(acc[mt][np * 2 + 1], ah[mt], bh[np] + 2);          \
                    mma16816(acc[mt][np * 2 + 1], ah[mt], bl[np] + 2);          \
                    mma16816(acc[mt][np * 2 + 1], al[mt], bh[np] + 2);          \
                }                                                               \
        }                                                                       \
    }

// ---- plain GEMM (fp32 C out) — used for the wo projection ----
__global__ void __launch_bounds__(512, 1) gemm_mma(
    const __nv_bfloat16* __restrict__ Ah, const __nv_bfloat16* __restrict__ Al,
    const __nv_bfloat16* __restrict__ Bh, const __nv_bfloat16* __restrict__ Bl,
    float* __restrict__ C, int M, int N, int K)
{
    GEMM_MAINLOOP(Ah, Al, Bh, Bl, K)
    #pragma unroll
    for (int mt = 0; mt < 2; mt++) {
        int r0 = m0 + wm + mt * 16 + (lane >> 2);
        #pragma unroll
        for (int nt = 0; nt < 4; nt++) {
            int c0 = n0 + wn + nt * 8 + (lane & 3) * 2;
            *(float2*)(C + (size_t)r0 * N + c0)       = make_float2(acc[mt][nt][0], acc[mt][nt][1]);
            *(float2*)(C + (size_t)(r0 + 8) * N + c0) = make_float2(acc[mt][nt][2], acc[mt][nt][3]);
        }
    }
}

// ---- qkv GEMM with fused RoPE + hi/lo split + relayout epilogue ----
// N is fixed = NQKV; each BN=128 column tile is exactly one head.
__global__ void __launch_bounds__(512, 1) gemm_qkv_rope(
    const __nv_bfloat16* __restrict__ Ah, const __nv_bfloat16* __restrict__ Al,
    const __nv_bfloat16* __restrict__ Bh, const __nv_bfloat16* __restrict__ Bl,
    const float* __restrict__ fcos, const float* __restrict__ fsin,
    __nv_bfloat16* __restrict__ qh, __nv_bfloat16* __restrict__ ql,
    __nv_bfloat16* __restrict__ kh, __nv_bfloat16* __restrict__ kl,
    __nv_bfloat16* __restrict__ vh, __nv_bfloat16* __restrict__ vl)
{
    GEMM_MAINLOOP(Ah, Al, Bh, Bl, DIM)
    const float qscale = 0.08838834764831845f;   // 1/sqrt(HD)
    #pragma unroll
    for (int mt = 0; mt < 2; mt++) {
        int r0 = m0 + wm + mt * 16 + (lane >> 2);
        #pragma unroll
        for (int half = 0; half < 2; half++) {
            int r = r0 + half * 8;
            int bb = r >> 11;                    // / SEQ
            int s  = r & (SEQ - 1);
            #pragma unroll
            for (int nt = 0; nt < 4; nt++) {
                int c0 = n0 + wn + nt * 8 + (lane & 3) * 2;
                float f0 = acc[mt][nt][half * 2];
                float f1 = acc[mt][nt][half * 2 + 1];
                int d = c0 & (HD - 1);
                int i2 = d >> 1;
                float outr, outi;
                __nv_bfloat16 *dh, *dl;
                size_t off;
                if (c0 < NQ) {                   // Q: rope + scale
                    float c = fcos[s * (HD/2) + i2], sn = fsin[s * (HD/2) + i2];
                    outr = (f0 * c - f1 * sn) * qscale;
                    outi = (f0 * sn + f1 * c) * qscale;
                    int hh = c0 >> 7;
                    off = ((size_t)(bb * NH + hh) * SEQ + s) * HD + d;
                    dh = qh; dl = ql;
                } else if (c0 < NQ + NKVD) {     // K: rope
                    float c = fcos[s * (HD/2) + i2], sn = fsin[s * (HD/2) + i2];
                    outr = f0 * c - f1 * sn;
                    outi = f0 * sn + f1 * c;
                    int hh = (c0 - NQ) >> 7;
                    off = ((size_t)(bb * NKV + hh) * SEQ + s) * HD + d;
                    dh = kh; dl = kl;
                } else {                         // V: passthrough
                    outr = f0; outi = f1;
                    int hh = (c0 - NQ - NKVD) >> 7;
                    off = ((size_t)(bb * NKV + hh) * SEQ + s) * HD + d;
                    dh = vh; dl = vl;
                }
                uint32_t hp = packbf(outr, outi);
                __nv_bfloat162 hb = *(__nv_bfloat162*)&hp;
                uint32_t lo = packbf(outr - __bfloat162float(hb.x),
                                     outi - __bfloat162float(hb.y));
                *(uint32_t*)(dh + off) = hp;
                *(uint32_t*)(dl + off) = lo;
            }
        }
    }
}

// ============================================================
// prep: fused x-split + qkv weight transpose + wo transpose (one launch)
// ============================================================
#define PREP_SPLIT_BLKS 32768
#define PREP_QKV_BLKS   24576
#define PREP_TOTAL      (PREP_SPLIT_BLKS + PREP_QKV_BLKS + 16384)

__global__ void __launch_bounds__(256) prep_kernel(
    const float* __restrict__ x,  const float* __restrict__ Wq,
    const float* __restrict__ Wk, const float* __restrict__ Wv,
    const float* __restrict__ Wo,
    __nv_bfloat16* __restrict__ xh,  __nv_bfloat16* __restrict__ xl,
    __nv_bfloat16* __restrict__ qkvTh, __nv_bfloat16* __restrict__ qkvTl,
    __nv_bfloat16* __restrict__ woTh,  __nv_bfloat16* __restrict__ woTl)
{
    __shared__ float tile[32][33];
    int bid = blockIdx.x, t = threadIdx.x;

    if (bid < PREP_SPLIT_BLKS) {
        int i = bid * 256 + t;
        float2 v = ((const float2*)x)[i];
        __nv_bfloat16 hx = __float2bfloat16(v.x), hy = __float2bfloat16(v.y);
        ((__nv_bfloat162*)xh)[i] = __halves2bfloat162(hx, hy);
        ((__nv_bfloat162*)xl)[i] = __halves2bfloat162(
            __float2bfloat16(v.x - __bfloat162float(hx)),
            __float2bfloat16(v.y - __bfloat162float(hy)));
        return;
    }

    int tx = t & 31, ty = t >> 5;
    const float* src; __nv_bfloat16 *Th, *Tl;
    int srcN, outK, nsrc, rowoff, by;
    if (bid < PREP_SPLIT_BLKS + PREP_QKV_BLKS) {
        int b2 = bid - PREP_SPLIT_BLKS;
        int bx = b2 % 192; by = b2 / 192;
        Th = qkvTh; Tl = qkvTl; outK = DIM;
        if (bx < 128)      { src = Wq; srcN = NQ;   nsrc = bx * 32;         rowoff = 0;    }
        else if (bx < 160) { src = Wk; srcN = NKVD; nsrc = (bx - 128) * 32; rowoff = NQ;   }
        else               { src = Wv; srcN = NKVD; nsrc = (bx - 160) * 32; rowoff = NQ + NKVD; }
    } else {
        int b2 = bid - PREP_SPLIT_BLKS - PREP_QKV_BLKS;
        int bx = b2 % 128; by = b2 / 128;
        Th = woTh; Tl = woTl; outK = NQ;
        src = Wo; srcN = DIM; nsrc = bx * 32; rowoff = 0;
    }

    int n = nsrc + tx;
    #pragma unroll
    for (int j = 0; j < 4; j++) {
        int k = by * 32 + ty + j * 8;
        tile[ty + j * 8][tx] = src[(size_t)k * srcN + n];
    }
    __syncthreads();
    int k2 = by * 32 + tx;
    #pragma unroll
    for (int j = 0; j < 4; j++) {
        int n2 = rowoff + nsrc + ty + j * 8;
        float v = tile[tx][ty + j * 8];
        __nv_bfloat16 h = __float2bfloat16(v);
        Th[(size_t)n2 * outK + k2] = h;
        Tl[(size_t)n2 * outK + k2] = __float2bfloat16(v - __bfloat162float(h));
    }
}

// ============================================================
// flash attention v4 (R11): 512 threads, 128 q-rows/CTA, no online max,
// register-resident P. UNCHANGED.
// ============================================================
#define NTILE (SEQ/64)
#define AKV_STG 65536u
#define AQ_OFF  131072u
#define ARED_OFF 196608u
#define ATT_SMEM 198656

__global__ void __launch_bounds__(512, 1) attn_mma(
    const __nv_bfloat16* __restrict__ qh, const __nv_bfloat16* __restrict__ ql,
    const __nv_bfloat16* __restrict__ kh, const __nv_bfloat16* __restrict__ kl,
    const __nv_bfloat16* __restrict__ vh, const __nv_bfloat16* __restrict__ vl,
    __nv_bfloat16* __restrict__ outh, __nv_bfloat16* __restrict__ outl)
{
    extern __shared__ char sm[];
    const uint32_t sb = smem_u32(sm);
    const int t = threadIdx.x, lane = t & 31, w = t >> 5;
    const int wm = w & 7, wn = w >> 3;
    const int qt = blockIdx.x, h = blockIdx.y, b = blockIdx.z;
    const int kvh = h >> 2;

    const __nv_bfloat16* qhg = qh + ((size_t)(b * NH + h) * SEQ + qt * 128) * HD;
    const __nv_bfloat16* qlg = ql + ((size_t)(b * NH + h) * SEQ + qt * 128) * HD;
    const size_t kvb = (size_t)(b * NKV + kvh) * SEQ * HD;

    {
        int r = t >> 2, seg = t & 3;
        #pragma unroll
        for (int j = 0; j < 4; j++) {
            int boff = seg * 64 + j * 16;
            uint4 a = *(const uint4*)(qhg + (size_t)r * HD + boff / 2);
            *(uint4*)(sm + AQ_OFF + sw256(r, boff)) = a;
            uint4 c = *(const uint4*)(qlg + (size_t)r * HD + boff / 2);
            *(uint4*)(sm + AQ_OFF + 32768u + sw256(r, boff)) = c;
        }
    }

    const int lrow = t >> 3, lsg = t & 7;
#define LOAD_KV(kt, stg) do {                                                   \
    uint32_t bufb = sb + (uint32_t)(stg) * AKV_STG;                             \
    size_t grow = kvb + ((size_t)(kt) * 64 + lrow) * HD;                        \
    _Pragma("unroll")                                                           \
    for (int j = 0; j < 2; j++) {                                               \
        int boff = lsg * 32 + j * 16;                                           \
        uint32_t sd = sw256(lrow, boff);                                        \
        cp16(bufb + sd,          kh + grow + boff / 2);                         \
        cp16(bufb + 16384u + sd, kl + grow + boff / 2);                         \
        cp16(bufb + 32768u + sd, vh + grow + boff / 2);                         \
        cp16(bufb + 49152u + sd, vl + grow + boff / 2);                         \
    }                                                                           \
} while (0)

    LOAD_KV(0, 0); CP_COMMIT();

    float lp[2] = {0.f, 0.f};
    float oacc[16][4];
    #pragma unroll
    for (int i = 0; i < 16; i++)
        #pragma unroll
        for (int j = 0; j < 4; j++) oacc[i][j] = 0.f;

    const int row1 = wm * 16 + (lane >> 2);
    const int row2 = row1 + 8;
    const int qar = wm * 16 + (lane & 7) + ((lane >> 3) & 1) * 8;
    const int qab = (lane >> 4) * 16;

    for (int kt = 0; kt < NTILE; kt++) {
        if (kt + 1 < NTILE) { LOAD_KV(kt + 1, (kt + 1) & 1); CP_COMMIT(); CP_WAIT1(); }
        else                { CP_WAIT0(); }
        __syncthreads();
        const uint32_t kbuf = sb + (uint32_t)(kt & 1) * AKV_STG;
        const uint32_t vbuf = kbuf + 32768u;

        float sacc[4][4];
        #pragma unroll
        for (int i = 0; i < 4; i++)
            #pragma unroll
            for (int j = 0; j < 4; j++) sacc[i][j] = 0.f;
        {
            int br = wn * 32 + (lane & 7) + (lane >> 4) * 8;
            int bb0 = ((lane >> 3) & 1) * 16;
            #pragma unroll
            for (int ks = 0; ks < 8; ks++) {
                uint32_t qfh[4], qfl[4];
                uint32_t qoff = sw256(qar, ks * 32 + qab);
                ldsm4(qfh, sb + AQ_OFF + qoff);
                ldsm4(qfl, sb + AQ_OFF + 32768u + qoff);
                #pragma unroll
                for (int np = 0; np < 2; np++) {
                    uint32_t bh[4], bl[4];
                    uint32_t off = sw256(br + np * 16, ks * 32 + bb0);
                    ldsm4(bh, kbuf + off);
                    ldsm4(bl, kbuf + 16384u + off);
                    mma16816(sacc[np * 2],     qfh, bh + 0);
                    mma16816(sacc[np * 2],     qfh, bl + 0);
                    mma16816(sacc[np * 2],     qfl, bh + 0);
                    mma16816(sacc[np * 2 + 1], qfh, bh + 2);
                    mma16816(sacc[np * 2 + 1], qfh, bl + 2);
                    mma16816(sacc[np * 2 + 1], qfl, bh + 2);
                }
            }
        }

        float p[4][4];
        #pragma unroll
        for (int nt = 0; nt < 4; nt++) {
            p[nt][0] = __expf(sacc[nt][0]);
            p[nt][1] = __expf(sacc[nt][1]);
            p[nt][2] = __expf(sacc[nt][2]);
            p[nt][3] = __expf(sacc[nt][3]);
            lp[0] += p[nt][0] + p[nt][1];
            lp[1] += p[nt][2] + p[nt][3];
        }

        {
            int vr0 = (lane & 7) + ((lane >> 3) & 1) * 8;
            int vc0 = (lane >> 4) * 16;
            #pragma unroll
            for (int kb = 0; kb < 2; kb++) {
                uint32_t pfh[4], pfl[4];
                {
                    const float* t0 = p[kb * 2];
                    const float* t1 = p[kb * 2 + 1];
                    pfh[0] = packbf(t0[0], t0[1]);
                    pfh[1] = packbf(t0[2], t0[3]);
                    pfh[2] = packbf(t1[0], t1[1]);
                    pfh[3] = packbf(t1[2], t1[3]);
                    __nv_bfloat162 h0 = *(__nv_bfloat162*)&pfh[0];
                    __nv_bfloat162 h1 = *(__nv_bfloat162*)&pfh[1];
                    __nv_bfloat162 h2 = *(__nv_bfloat162*)&pfh[2];
                    __nv_bfloat162 h3 = *(__nv_bfloat162*)&pfh[3];
                    pfl[0] = packbf(t0[0] - __bfloat162float(h0.x), t0[1] - __bfloat162float(h0.y));
                    pfl[1] = packbf(t0[2] - __bfloat162float(h1.x), t0[3] - __bfloat162float(h1.y));
                    pfl[2] = packbf(t1[0] - __bfloat162float(h2.x), t1[1] - __bfloat162float(h2.y));
                    pfl[3] = packbf(t1[2] - __bfloat162float(h3.x), t1[3] - __bfloat162float(h3.y));
                }
                int vrow = wn * 32 + kb * 16 + vr0;
                #pragma unroll
                for (int db = 0; db < 8; db++) {
                    uint32_t wh[4], wl[4];
                    uint32_t off = sw256(vrow, db * 32 + vc0);
                    ldsm4t(wh, vbuf + off);
                    ldsm4t(wl, vbuf + 16384u + off);
                    mma16816(oacc[db * 2],     pfh, wh + 0);
                    mma16816(oacc[db * 2],     pfh, wl + 0);
                    mma16816(oacc[db * 2],     pfl, wh + 0);
                    mma16816(oacc[db * 2 + 1], pfh, wh + 2);
                    mma16816(oacc[db * 2 + 1], pfh, wl + 2);
                    mma16816(oacc[db * 2 + 1], pfl, wh + 2);
                }
            }
        }
        __syncthreads();
    }

    {
        lp[0] += __shfl_xor_sync(0xffffffffu, lp[0], 1);
        lp[0] += __shfl_xor_sync(0xffffffffu, lp[0], 2);
        lp[1] += __shfl_xor_sync(0xffffffffu, lp[1], 1);
        lp[1] += __shfl_xor_sync(0xffffffffu, lp[1], 2);
        float* reds = (float*)(sm + ARED_OFF);
        if ((lane & 3) == 0) {
            reds[wn * 128 + row1] = lp[0];
            reds[wn * 128 + row2] = lp[1];
        }
        float* ox = (float*)sm;
        if (wn == 1) {
            #pragma unroll
            for (int nt = 0; nt < 16; nt++) {
                int c0 = nt * 8 + (lane & 3) * 2;
                *(float2*)(ox + (size_t)row1 * 128 + c0) = make_float2(oacc[nt][0], oacc[nt][1]);
                *(float2*)(ox + (size_t)row2 * 128 + c0) = make_float2(oacc[nt][2], oacc[nt][3]);
            }
        }
        __syncthreads();
        if (wn == 0) {
            float inv1 = 1.f / (reds[row1] + reds[128 + row1]);
            float inv2 = 1.f / (reds[row2] + reds[128 + row2]);
            int rg1 = qt * 128 + row1, rg2 = qt * 128 + row2;
            size_t b1 = ((size_t)(b * SEQ + rg1) * NH + h) * HD;
            size_t b2 = ((size_t)(b * SEQ + rg2) * NH + h) * HD;
            #pragma unroll
            for (int nt = 0; nt < 16; nt++) {
                int c0 = nt * 8 + (lane & 3) * 2;
                float2 x1 = *(float2*)(ox + (size_t)row1 * 128 + c0);
                float2 x2 = *(float2*)(ox + (size_t)row2 * 128 + c0);
                float f0 = (oacc[nt][0] + x1.x) * inv1;
                float f1 = (oacc[nt][1] + x1.y) * inv1;
                float f2 = (oacc[nt][2] + x2.x) * inv2;
                float f3 = (oacc[nt][3] + x2.y) * inv2;
                uint32_t h01 = packbf(f0, f1), h23 = packbf(f2, f3);
                __nv_bfloat162 bb01 = *(__nv_bfloat162*)&h01;
                __nv_bfloat162 bb23 = *(__nv_bfloat162*)&h23;
                uint32_t l01 = packbf(f0 - __bfloat162float(bb01.x), f1 - __bfloat162float(bb01.y));
                uint32_t l23 = packbf(f2 - __bfloat162float(bb23.x), f3 - __bfloat162float(bb23.y));
                *(uint32_t*)(outh + b1 + c0) = h01;
                *(uint32_t*)(outh + b2 + c0) = h23;
                *(uint32_t*)(outl + b1 + c0) = l01;
                *(uint32_t*)(outl + b2 + c0) = l23;
            }
        }
    }
#undef LOAD_KV
}

// ============================================================
// launch  (launches: 0 prep, 1 gemm_qkv_rope, 2 attn, 3 gemm_wo <- ncu slot)
// ============================================================
extern "C" void kernel_launch(void* const* d_in, const int* in_sizes, int n_in,
                              void* d_out, int out_size)
{
    const float* x  = (const float*)d_in[0];
    const float* wq = (const float*)d_in[1];
    const float* wk = (const float*)d_in[2];
    const float* wv = (const float*)d_in[3];
    const float* wo = (const float*)d_in[4];
    const float* fcos = (const float*)d_in[7];
    const float* fsin = (const float*)d_in[8];
    float* out = (float*)d_out;

    __nv_bfloat16 *xh, *xl, *wqkvTh, *wqkvTl, *woTh, *woTl;
    __nv_bfloat16 *aoh, *aol, *pqh, *pql, *pkh, *pkl, *pvh, *pvl;
    cudaGetSymbolAddress((void**)&xh, g_xh);         cudaGetSymbolAddress((void**)&xl, g_xl);
    cudaGetSymbolAddress((void**)&wqkvTh, g_wqkvTh); cudaGetSymbolAddress((void**)&wqkvTl, g_wqkvTl);
    cudaGetSymbolAddress((void**)&woTh, g_woTh);     cudaGetSymbolAddress((void**)&woTl, g_woTl);
    cudaGetSymbolAddress((void**)&aoh, g_aoh);       cudaGetSymbolAddress((void**)&aol, g_aol);
    cudaGetSymbolAddress((void**)&pqh, g_qh);        cudaGetSymbolAddress((void**)&pql, g_ql);
    cudaGetSymbolAddress((void**)&pkh, g_kh);        cudaGetSymbolAddress((void**)&pkl, g_kl);
    cudaGetSymbolAddress((void**)&pvh, g_vh);        cudaGetSymbolAddress((void**)&pvl, g_vl);

    cudaFuncSetAttribute(gemm_mma,      cudaFuncAttributeMaxDynamicSharedMemorySize, GEMM_SMEM);
    cudaFuncSetAttribute(gemm_qkv_rope, cudaFuncAttributeMaxDynamicSharedMemorySize, GEMM_SMEM);
    cudaFuncSetAttribute(attn_mma,      cudaFuncAttributeMaxDynamicSharedMemorySize, ATT_SMEM);

    // 0: prep (x split + all weight transposes)
    prep_kernel<<<PREP_TOTAL, 256>>>(x, wq, wk, wv, wo, xh, xl, wqkvTh, wqkvTl, woTh, woTl);
    // 1: fused qkv projection + rope + split + relayout
    gemm_qkv_rope<<<dim3(NQKV / BN, MTOT / BM), 512, GEMM_SMEM>>>(
        xh, xl, wqkvTh, wqkvTl, fcos, fsin, pqh, pql, pkh, pkl, pvh, pvl);
    // 2: attention
    {
        dim3 grid(SEQ / 128, NH, BATCH);
        attn_mma<<<grid, 512, ATT_SMEM>>>(pqh, pql, pkh, pkl, pvh, pvl, aoh, aol);
    }
    // 3: output projection  <-- ncu capture slot
    gemm_mma<<<dim3(DIM / BN, MTOT / BM), 512, GEMM_SMEM>>>(aoh, aol, woTh, woTl, out, MTOT, DIM, NQ);
}

// round 13
// speedup vs baseline: 1.0582x; 1.0582x over previous
#include <cuda_runtime.h>
#include <cuda_bf16.h>
#include <cstdint>
#include <math.h>

#define BATCH 2
#define SEQ   2048
#define DIM   4096
#define NH    32
#define NKV   8
#define HD    128
#define NREP  4
#define MTOT  (BATCH*SEQ)   // 4096
#define NQ    (NH*HD)       // 4096
#define NKVD  (NKV*HD)      // 1024
#define NQKV  (NQ + 2*NKVD) // 6144

// -------- scratch (device globals) --------
__device__ __nv_bfloat16 g_xh[(size_t)MTOT*DIM],   g_xl[(size_t)MTOT*DIM];
__device__ __nv_bfloat16 g_wqkvTh[(size_t)NQKV*DIM], g_wqkvTl[(size_t)NQKV*DIM];
__device__ __nv_bfloat16 g_woTh[(size_t)DIM*NQ],   g_woTl[(size_t)DIM*NQ];
__device__ __nv_bfloat16 g_aoh[(size_t)MTOT*NQ],   g_aol[(size_t)MTOT*NQ];
__device__ __nv_bfloat16 g_qh[(size_t)MTOT*NQ],    g_ql[(size_t)MTOT*NQ];
__device__ __nv_bfloat16 g_kh[(size_t)MTOT*NKVD],  g_kl[(size_t)MTOT*NKVD];
__device__ __nv_bfloat16 g_vh[(size_t)MTOT*NKVD],  g_vl[(size_t)MTOT*NKVD];

// ============================================================
// PTX helpers
// ============================================================
__device__ __forceinline__ uint32_t smem_u32(const void* p) {
    uint32_t a;
    asm("{ .reg .u64 t; cvta.to.shared.u64 t, %1; cvt.u32.u64 %0, t; }" : "=r"(a) : "l"(p));
    return a;
}
__device__ __forceinline__ void cp16(uint32_t dst, const void* src) {
    asm volatile("cp.async.cg.shared.global [%0], [%1], 16;" :: "r"(dst), "l"(src));
}
#define CP_COMMIT()  asm volatile("cp.async.commit_group;")
#define CP_WAIT1()   asm volatile("cp.async.wait_group 1;")
#define CP_WAIT0()   asm volatile("cp.async.wait_group 0;")

__device__ __forceinline__ void ldsm4(uint32_t* r, uint32_t addr) {
    asm volatile("ldmatrix.sync.aligned.m8n8.x4.shared.b16 {%0,%1,%2,%3}, [%4];"
        : "=r"(r[0]), "=r"(r[1]), "=r"(r[2]), "=r"(r[3]) : "r"(addr));
}
__device__ __forceinline__ void ldsm4t(uint32_t* r, uint32_t addr) {
    asm volatile("ldmatrix.sync.aligned.m8n8.x4.trans.shared.b16 {%0,%1,%2,%3}, [%4];"
        : "=r"(r[0]), "=r"(r[1]), "=r"(r[2]), "=r"(r[3]) : "r"(addr));
}
__device__ __forceinline__ void mma16816(float* c, const uint32_t* a, const uint32_t* b) {
    asm volatile("mma.sync.aligned.m16n8k16.row.col.f32.bf16.bf16.f32 "
        "{%0,%1,%2,%3}, {%4,%5,%6,%7}, {%8,%9}, {%0,%1,%2,%3};"
        : "+f"(c[0]), "+f"(c[1]), "+f"(c[2]), "+f"(c[3])
        : "r"(a[0]), "r"(a[1]), "r"(a[2]), "r"(a[3]), "r"(b[0]), "r"(b[1]));
}
__device__ __forceinline__ uint32_t packbf(float a, float b) {
    __nv_bfloat162 v = __floats2bfloat162_rn(a, b);
    return *(uint32_t*)&v;
}

__device__ __forceinline__ uint32_t swz(int row, int seg) {     // 64B rows, 4 segs
    return (uint32_t)row * 64u + ((uint32_t)(seg ^ ((row >> 1) & 3)) << 4);
}
__device__ __forceinline__ uint32_t sw256(int row, int boff) {
    return (uint32_t)row * 256u + (uint32_t)(boff ^ ((row & 7) << 4));
}

// ============================================================
// GEMM mainloop (R7/R11 PROVEN 2-stage, BK=32): CTA 128x128,
// 512 threads (16 warps 4x4), warp tile 32x32, 2 barriers/chunk.
// ============================================================
#define BM 128
#define BN 128
#define BK 32
#define GOFF_AH 0u
#define GOFF_AL 8192u
#define GOFF_BH 16384u
#define GOFF_BL 24576u
#define GSTAGE  32768u
#define GEMM_SMEM (2*32768)

#define GEMM_MAINLOOP(Ah, Al, Bh, Bl, Kdim)                                     \
    extern __shared__ char smem[];                                              \
    const uint32_t sb = smem_u32(smem);                                         \
    const int t = threadIdx.x;                                                  \
    const int lane = t & 31, wid = t >> 5;                                      \
    const int m0 = blockIdx.y * BM, n0 = blockIdx.x * BN;                       \
    const int lrow = t >> 2, lseg = t & 3;                                      \
    const __nv_bfloat16* gAh = (Ah) + (size_t)(m0 + lrow) * (Kdim) + lseg * 8;  \
    const __nv_bfloat16* gAl = (Al) + (size_t)(m0 + lrow) * (Kdim) + lseg * 8;  \
    const __nv_bfloat16* gBh = (Bh) + (size_t)(n0 + lrow) * (Kdim) + lseg * 8;  \
    const __nv_bfloat16* gBl = (Bl) + (size_t)(n0 + lrow) * (Kdim) + lseg * 8;  \
    const uint32_t loff = swz(lrow, lseg);                                      \
    const int wm = (wid & 3) * 32;                                              \
    const int wn = (wid >> 2) * 32;                                             \
    const int arow = wm + (lane & 7) + ((lane >> 3) & 1) * 8;                   \
    const int aseg = lane >> 4;                                                 \
    const int brow = wn + (lane & 7) + ((lane >> 4) & 1) * 8;                   \
    const int bseg = (lane >> 3) & 1;                                           \
    float acc[2][4][4];                                                         \
    _Pragma("unroll")                                                           \
    for (int i = 0; i < 2; i++)                                                 \
        _Pragma("unroll")                                                       \
        for (int j = 0; j < 4; j++)                                             \
            _Pragma("unroll")                                                   \
            for (int v = 0; v < 4; v++) acc[i][j][v] = 0.f;                     \
    const int nch = (Kdim) / BK;                                                \
    {                                                                           \
        cp16(sb + GOFF_AH + loff, gAh); cp16(sb + GOFF_AL + loff, gAl);         \
        cp16(sb + GOFF_BH + loff, gBh); cp16(sb + GOFF_BL + loff, gBl);         \
        CP_COMMIT();                                                            \
        uint32_t b1 = sb + GSTAGE;                                              \
        cp16(b1 + GOFF_AH + loff, gAh + BK); cp16(b1 + GOFF_AL + loff, gAl + BK);\
        cp16(b1 + GOFF_BH + loff, gBh + BK); cp16(b1 + GOFF_BL + loff, gBl + BK);\
        CP_COMMIT();                                                            \
    }                                                                           \
    for (int ch = 0; ch < nch; ch++) {                                          \
        CP_WAIT1();                                                             \
        __syncthreads();                                                        \
        const uint32_t base = sb + (uint32_t)(ch & 1) * GSTAGE;                 \
        _Pragma("unroll")                                                       \
        for (int ks = 0; ks < 2; ks++) {                                        \
            uint32_t ah[2][4], al[2][4], bh[2][4], bl[2][4];                    \
            _Pragma("unroll")                                                   \
            for (int mt = 0; mt < 2; mt++) {                                    \
                uint32_t off = swz(arow + mt * 16, ks * 2 + aseg);              \
                ldsm4(ah[mt], base + GOFF_AH + off);                            \
                ldsm4(al[mt], base + GOFF_AL + off);                            \
            }                                                                   \
            _Pragma("unroll")                                                   \
            for (int np = 0; np < 2; np++) {                                    \
                uint32_t off = swz(brow + np * 16, ks * 2 + bseg);              \
                ldsm4(bh[np], base + GOFF_BH + off);                            \
                ldsm4(bl[np], base + GOFF_BL + off);                            \
            }                                                                   \
            _Pragma("unroll")                                                   \
            for (int np = 0; np < 2; np++)                                      \
                _Pragma("unroll")                                               \
                for (int mt = 0; mt < 2; mt++) {                                \
                    mma16816(acc[mt][np * 2],     ah[mt], bh[np] + 0);          \
                    mma16816(acc[mt][np * 2],     ah[mt], bl[np] + 0);          \
                    mma16816(acc[mt][np * 2],     al[mt], bh[np] + 0);          \
                    mma16816(acc[mt][np * 2 + 1], ah[mt], bh[np] + 2);          \
                    mma16816(acc[mt][np * 2 + 1], ah[mt], bl[np] + 2);          \
                    mma16816(acc[mt][np * 2 + 1], al[mt], bh[np] + 2);          \
                }                                                               \
        }                                                                       \
        __syncthreads();                                                        \
        if (ch + 2 < nch) {                                                     \
            int k0 = (ch + 2) * BK;                                             \
            cp16(base + GOFF_AH + loff, gAh + k0); cp16(base + GOFF_AL + loff, gAl + k0);\
            cp16(base + GOFF_BH + loff, gBh + k0); cp16(base + GOFF_BL + loff, gBl + k0);\
        }                                                                       \
        CP_COMMIT();                                                            \
    }

// ---- plain GEMM (fp32 C out) — wo projection (byte-identical to R11) ----
__global__ void __launch_bounds__(512, 1) gemm_mma(
    const __nv_bfloat16* __restrict__ Ah, const __nv_bfloat16* __restrict__ Al,
    const __nv_bfloat16* __restrict__ Bh, const __nv_bfloat16* __restrict__ Bl,
    float* __restrict__ C, int M, int N, int K)
{
    GEMM_MAINLOOP(Ah, Al, Bh, Bl, K)
    #pragma unroll
    for (int mt = 0; mt < 2; mt++) {
        int r0 = m0 + wm + mt * 16 + (lane >> 2);
        #pragma unroll
        for (int nt = 0; nt < 4; nt++) {
            int c0 = n0 + wn + nt * 8 + (lane & 3) * 2;
            *(float2*)(C + (size_t)r0 * N + c0)       = make_float2(acc[mt][nt][0], acc[mt][nt][1]);
            *(float2*)(C + (size_t)(r0 + 8) * N + c0) = make_float2(acc[mt][nt][2], acc[mt][nt][3]);
        }
    }
}

// ---- qkv GEMM + fused RoPE/split/relayout; CTA-uniform region logic ----
__global__ void __launch_bounds__(512, 1) gemm_qkv_rope(
    const __nv_bfloat16* __restrict__ Ah, const __nv_bfloat16* __restrict__ Al,
    const __nv_bfloat16* __restrict__ Bh, const __nv_bfloat16* __restrict__ Bl,
    const float* __restrict__ fcos, const float* __restrict__ fsin,
    __nv_bfloat16* __restrict__ qh, __nv_bfloat16* __restrict__ ql,
    __nv_bfloat16* __restrict__ kh, __nv_bfloat16* __restrict__ kl,
    __nv_bfloat16* __restrict__ vh, __nv_bfloat16* __restrict__ vl)
{
    GEMM_MAINLOOP(Ah, Al, Bh, Bl, DIM)

    // ---- CTA-uniform epilogue config (n0 selects region & head) ----
    __nv_bfloat16 *dh, *dl;
    int do_rope;
    float scale;
    uint32_t headSeqBase;                 // (bh_idx)*SEQ, where bh_idx folds batch+head
    if (n0 < NQ) {
        dh = qh; dl = ql; do_rope = 1; scale = 0.08838834764831845f;
        headSeqBase = (uint32_t)(n0 >> 7) * SEQ;            // head * SEQ (batch added per row)
    } else if (n0 < NQ + NKVD) {
        dh = kh; dl = kl; do_rope = 1; scale = 1.0f;
        headSeqBase = (uint32_t)((n0 - NQ) >> 7) * SEQ;
    } else {
        dh = vh; dl = vl; do_rope = 0; scale = 1.0f;
        headSeqBase = (uint32_t)((n0 - NQ - NKVD) >> 7) * SEQ;
    }
    const uint32_t batchStride = (n0 < NQ) ? (uint32_t)NH * SEQ : (uint32_t)NKV * SEQ;

    #pragma unroll
    for (int mt = 0; mt < 2; mt++) {
        int r0 = wm + mt * 16 + (lane >> 2);               // row within CTA tile
        #pragma unroll
        for (int half = 0; half < 2; half++) {
            int r = m0 + r0 + half * 8;                    // global row
            uint32_t bb = (uint32_t)r >> 11;               // batch
            uint32_t s  = (uint32_t)r & (SEQ - 1);
            uint32_t rowBase = (bb * batchStride + headSeqBase + s) * HD;
            const float* crow = fcos + s * (HD / 2);
            const float* srow = fsin + s * (HD / 2);
            #pragma unroll
            for (int nt = 0; nt < 4; nt++) {
                int d = wn + nt * 8 + (lane & 3) * 2;      // 0..127, even
                float f0 = acc[mt][nt][half * 2];
                float f1 = acc[mt][nt][half * 2 + 1];
                float outr, outi;
                if (do_rope) {
                    float c = crow[d >> 1], sn = srow[d >> 1];
                    outr = (f0 * c - f1 * sn) * scale;
                    outi = (f0 * sn + f1 * c) * scale;
                } else {
                    outr = f0; outi = f1;
                }
                uint32_t hp = packbf(outr, outi);
                __nv_bfloat162 hb = *(__nv_bfloat162*)&hp;
                uint32_t lo = packbf(outr - __bfloat162float(hb.x),
                                     outi - __bfloat162float(hb.y));
                *(uint32_t*)(dh + rowBase + d) = hp;
                *(uint32_t*)(dl + rowBase + d) = lo;
            }
        }
    }
}

// ============================================================
// prep: fused x-split + qkv weight transpose + wo transpose (one launch)
// ============================================================
#define PREP_SPLIT_BLKS 32768
#define PREP_QKV_BLKS   24576
#define PREP_TOTAL      (PREP_SPLIT_BLKS + PREP_QKV_BLKS + 16384)

__global__ void __launch_bounds__(256) prep_kernel(
    const float* __restrict__ x,  const float* __restrict__ Wq,
    const float* __restrict__ Wk, const float* __restrict__ Wv,
    const float* __restrict__ Wo,
    __nv_bfloat16* __restrict__ xh,  __nv_bfloat16* __restrict__ xl,
    __nv_bfloat16* __restrict__ qkvTh, __nv_bfloat16* __restrict__ qkvTl,
    __nv_bfloat16* __restrict__ woTh,  __nv_bfloat16* __restrict__ woTl)
{
    __shared__ float tile[32][33];
    int bid = blockIdx.x, t = threadIdx.x;

    if (bid < PREP_SPLIT_BLKS) {
        int i = bid * 256 + t;
        float2 v = ((const float2*)x)[i];
        __nv_bfloat16 hx = __float2bfloat16(v.x), hy = __float2bfloat16(v.y);
        ((__nv_bfloat162*)xh)[i] = __halves2bfloat162(hx, hy);
        ((__nv_bfloat162*)xl)[i] = __halves2bfloat162(
            __float2bfloat16(v.x - __bfloat162float(hx)),
            __float2bfloat16(v.y - __bfloat162float(hy)));
        return;
    }

    int tx = t & 31, ty = t >> 5;
    const float* src; __nv_bfloat16 *Th, *Tl;
    int srcN, outK, nsrc, rowoff, by;
    if (bid < PREP_SPLIT_BLKS + PREP_QKV_BLKS) {
        int b2 = bid - PREP_SPLIT_BLKS;
        int bx = b2 % 192; by = b2 / 192;
        Th = qkvTh; Tl = qkvTl; outK = DIM;
        if (bx < 128)      { src = Wq; srcN = NQ;   nsrc = bx * 32;         rowoff = 0;    }
        else if (bx < 160) { src = Wk; srcN = NKVD; nsrc = (bx - 128) * 32; rowoff = NQ;   }
        else               { src = Wv; srcN = NKVD; nsrc = (bx - 160) * 32; rowoff = NQ + NKVD; }
    } else {
        int b2 = bid - PREP_SPLIT_BLKS - PREP_QKV_BLKS;
        int bx = b2 % 128; by = b2 / 128;
        Th = woTh; Tl = woTl; outK = NQ;
        src = Wo; srcN = DIM; nsrc = bx * 32; rowoff = 0;
    }

    int n = nsrc + tx;
    #pragma unroll
    for (int j = 0; j < 4; j++) {
        int k = by * 32 + ty + j * 8;
        tile[ty + j * 8][tx] = src[(size_t)k * srcN + n];
    }
    __syncthreads();
    int k2 = by * 32 + tx;
    #pragma unroll
    for (int j = 0; j < 4; j++) {
        int n2 = rowoff + nsrc + ty + j * 8;
        float v = tile[tx][ty + j * 8];
        __nv_bfloat16 h = __float2bfloat16(v);
        Th[(size_t)n2 * outK + k2] = h;
        Tl[(size_t)n2 * outK + k2] = __float2bfloat16(v - __bfloat162float(h));
    }
}

// ============================================================
// flash attention v4 (R11 winner, byte-identical)
// ============================================================
#define NTILE (SEQ/64)
#define AKV_STG 65536u
#define AQ_OFF  131072u
#define ARED_OFF 196608u
#define ATT_SMEM 198656

__global__ void __launch_bounds__(512, 1) attn_mma(
    const __nv_bfloat16* __restrict__ qh, const __nv_bfloat16* __restrict__ ql,
    const __nv_bfloat16* __restrict__ kh, const __nv_bfloat16* __restrict__ kl,
    const __nv_bfloat16* __restrict__ vh, const __nv_bfloat16* __restrict__ vl,
    __nv_bfloat16* __restrict__ outh, __nv_bfloat16* __restrict__ outl)
{
    extern __shared__ char sm[];
    const uint32_t sb = smem_u32(sm);
    const int t = threadIdx.x, lane = t & 31, w = t >> 5;
    const int wm = w & 7, wn = w >> 3;
    const int qt = blockIdx.x, h = blockIdx.y, b = blockIdx.z;
    const int kvh = h >> 2;

    const __nv_bfloat16* qhg = qh + ((size_t)(b * NH + h) * SEQ + qt * 128) * HD;
    const __nv_bfloat16* qlg = ql + ((size_t)(b * NH + h) * SEQ + qt * 128) * HD;
    const size_t kvb = (size_t)(b * NKV + kvh) * SEQ * HD;

    {
        int r = t >> 2, seg = t & 3;
        #pragma unroll
        for (int j = 0; j < 4; j++) {
            int boff = seg * 64 + j * 16;
            uint4 a = *(const uint4*)(qhg + (size_t)r * HD + boff / 2);
            *(uint4*)(sm + AQ_OFF + sw256(r, boff)) = a;
            uint4 c = *(const uint4*)(qlg + (size_t)r * HD + boff / 2);
            *(uint4*)(sm + AQ_OFF + 32768u + sw256(r, boff)) = c;
        }
    }

    const int lrow = t >> 3, lsg = t & 7;
#define LOAD_KV(kt, stg) do {                                                   \
    uint32_t bufb = sb + (uint32_t)(stg) * AKV_STG;                             \
    size_t grow = kvb + ((size_t)(kt) * 64 + lrow) * HD;                        \
    _Pragma("unroll")                                                           \
    for (int j = 0; j < 2; j++) {                                               \
        int boff = lsg * 32 + j * 16;                                           \
        uint32_t sd = sw256(lrow, boff);                                        \
        cp16(bufb + sd,          kh + grow + boff / 2);                         \
        cp16(bufb + 16384u + sd, kl + grow + boff / 2);                         \
        cp16(bufb + 32768u + sd, vh + grow + boff / 2);                         \
        cp16(bufb + 49152u + sd, vl + grow + boff / 2);                         \
    }                                                                           \
} while (0)

    LOAD_KV(0, 0); CP_COMMIT();

    float lp[2] = {0.f, 0.f};
    float oacc[16][4];
    #pragma unroll
    for (int i = 0; i < 16; i++)
        #pragma unroll
        for (int j = 0; j < 4; j++) oacc[i][j] = 0.f;

    const int row1 = wm * 16 + (lane >> 2);
    const int row2 = row1 + 8;
    const int qar = wm * 16 + (lane & 7) + ((lane >> 3) & 1) * 8;
    const int qab = (lane >> 4) * 16;

    for (int kt = 0; kt < NTILE; kt++) {
        if (kt + 1 < NTILE) { LOAD_KV(kt + 1, (kt + 1) & 1); CP_COMMIT(); CP_WAIT1(); }
        else                { CP_WAIT0(); }
        __syncthreads();
        const uint32_t kbuf = sb + (uint32_t)(kt & 1) * AKV_STG;
        const uint32_t vbuf = kbuf + 32768u;

        float sacc[4][4];
        #pragma unroll
        for (int i = 0; i < 4; i++)
            #pragma unroll
            for (int j = 0; j < 4; j++) sacc[i][j] = 0.f;
        {
            int br = wn * 32 + (lane & 7) + (lane >> 4) * 8;
            int bb0 = ((lane >> 3) & 1) * 16;
            #pragma unroll
            for (int ks = 0; ks < 8; ks++) {
                uint32_t qfh[4], qfl[4];
                uint32_t qoff = sw256(qar, ks * 32 + qab);
                ldsm4(qfh, sb + AQ_OFF + qoff);
                ldsm4(qfl, sb + AQ_OFF + 32768u + qoff);
                #pragma unroll
                for (int np = 0; np < 2; np++) {
                    uint32_t bh[4], bl[4];
                    uint32_t off = sw256(br + np * 16, ks * 32 + bb0);
                    ldsm4(bh, kbuf + off);
                    ldsm4(bl, kbuf + 16384u + off);
                    mma16816(sacc[np * 2],     qfh, bh + 0);
                    mma16816(sacc[np * 2],     qfh, bl + 0);
                    mma16816(sacc[np * 2],     qfl, bh + 0);
                    mma16816(sacc[np * 2 + 1], qfh, bh + 2);
                    mma16816(sacc[np * 2 + 1], qfh, bl + 2);
                    mma16816(sacc[np * 2 + 1], qfl, bh + 2);
                }
            }
        }

        float p[4][4];
        #pragma unroll
        for (int nt = 0; nt < 4; nt++) {
            p[nt][0] = __expf(sacc[nt][0]);
            p[nt][1] = __expf(sacc[nt][1]);
            p[nt][2] = __expf(sacc[nt][2]);
            p[nt][3] = __expf(sacc[nt][3]);
            lp[0] += p[nt][0] + p[nt][1];
            lp[1] += p[nt][2] + p[nt][3];
        }

        {
            int vr0 = (lane & 7) + ((lane >> 3) & 1) * 8;
            int vc0 = (lane >> 4) * 16;
            #pragma unroll
            for (int kb = 0; kb < 2; kb++) {
                uint32_t pfh[4], pfl[4];
                {
                    const float* t0 = p[kb * 2];
                    const float* t1 = p[kb * 2 + 1];
                    pfh[0] = packbf(t0[0], t0[1]);
                    pfh[1] = packbf(t0[2], t0[3]);
                    pfh[2] = packbf(t1[0], t1[1]);
                    pfh[3] = packbf(t1[2], t1[3]);
                    __nv_bfloat162 h0 = *(__nv_bfloat162*)&pfh[0];
                    __nv_bfloat162 h1 = *(__nv_bfloat162*)&pfh[1];
                    __nv_bfloat162 h2 = *(__nv_bfloat162*)&pfh[2];
                    __nv_bfloat162 h3 = *(__nv_bfloat162*)&pfh[3];
                    pfl[0] = packbf(t0[0] - __bfloat162float(h0.x), t0[1] - __bfloat162float(h0.y));
                    pfl[1] = packbf(t0[2] - __bfloat162float(h1.x), t0[3] - __bfloat162float(h1.y));
                    pfl[2] = packbf(t1[0] - __bfloat162float(h2.x), t1[1] - __bfloat162float(h2.y));
                    pfl[3] = packbf(t1[2] - __bfloat162float(h3.x), t1[3] - __bfloat162float(h3.y));
                }
                int vrow = wn * 32 + kb * 16 + vr0;
                #pragma unroll
                for (int db = 0; db < 8; db++) {
                    uint32_t wh[4], wl[4];
                    uint32_t off = sw256(vrow, db * 32 + vc0);
                    ldsm4t(wh, vbuf + off);
                    ldsm4t(wl, vbuf + 16384u + off);
                    mma16816(oacc[db * 2],     pfh, wh + 0);
                    mma16816(oacc[db * 2],     pfh, wl + 0);
                    mma16816(oacc[db * 2],     pfl, wh + 0);
                    mma16816(oacc[db * 2 + 1], pfh, wh + 2);
                    mma16816(oacc[db * 2 + 1], pfh, wl + 2);
                    mma16816(oacc[db * 2 + 1], pfl, wh + 2);
                }
            }
        }
        __syncthreads();
    }

    {
        lp[0] += __shfl_xor_sync(0xffffffffu, lp[0], 1);
        lp[0] += __shfl_xor_sync(0xffffffffu, lp[0], 2);
        lp[1] += __shfl_xor_sync(0xffffffffu, lp[1], 1);
        lp[1] += __shfl_xor_sync(0xffffffffu, lp[1], 2);
        float* reds = (float*)(sm + ARED_OFF);
        if ((lane & 3) == 0) {
            reds[wn * 128 + row1] = lp[0];
            reds[wn * 128 + row2] = lp[1];
        }
        float* ox = (float*)sm;
        if (wn == 1) {
            #pragma unroll
            for (int nt = 0; nt < 16; nt++) {
                int c0 = nt * 8 + (lane & 3) * 2;
                *(float2*)(ox + (size_t)row1 * 128 + c0) = make_float2(oacc[nt][0], oacc[nt][1]);
                *(float2*)(ox + (size_t)row2 * 128 + c0) = make_float2(oacc[nt][2], oacc[nt][3]);
            }
        }
        __syncthreads();
        if (wn == 0) {
            float inv1 = 1.f / (reds[row1] + reds[128 + row1]);
            float inv2 = 1.f / (reds[row2] + reds[128 + row2]);
            int rg1 = qt * 128 + row1, rg2 = qt * 128 + row2;
            size_t b1 = ((size_t)(b * SEQ + rg1) * NH + h) * HD;
            size_t b2 = ((size_t)(b * SEQ + rg2) * NH + h) * HD;
            #pragma unroll
            for (int nt = 0; nt < 16; nt++) {
                int c0 = nt * 8 + (lane & 3) * 2;
                float2 x1 = *(float2*)(ox + (size_t)row1 * 128 + c0);
                float2 x2 = *(float2*)(ox + (size_t)row2 * 128 + c0);
                float f0 = (oacc[nt][0] + x1.x) * inv1;
                float f1 = (oacc[nt][1] + x1.y) * inv1;
                float f2 = (oacc[nt][2] + x2.x) * inv2;
                float f3 = (oacc[nt][3] + x2.y) * inv2;
                uint32_t h01 = packbf(f0, f1), h23 = packbf(f2, f3);
                __nv_bfloat162 bb01 = *(__nv_bfloat162*)&h01;
                __nv_bfloat162 bb23 = *(__nv_bfloat162*)&h23;
                uint32_t l01 = packbf(f0 - __bfloat162float(bb01.x), f1 - __bfloat162float(bb01.y));
                uint32_t l23 = packbf(f2 - __bfloat162float(bb23.x), f3 - __bfloat162float(bb23.y));
                *(uint32_t*)(outh + b1 + c0) = h01;
                *(uint32_t*)(outh + b2 + c0) = h23;
                *(uint32_t*)(outl + b1 + c0) = l01;
                *(uint32_t*)(outl + b2 + c0) = l23;
            }
        }
    }
#undef LOAD_KV
}

// ============================================================
// launch  (0 prep, 1 gemm_qkv_rope, 2 attn, 3 gemm_wo <- ncu slot)
// ============================================================
extern "C" void kernel_launch(void* const* d_in, const int* in_sizes, int n_in,
                              void* d_out, int out_size)
{
    const float* x  = (const float*)d_in[0];
    const float* wq = (const float*)d_in[1];
    const float* wk = (const float*)d_in[2];
    const float* wv = (const float*)d_in[3];
    const float* wo = (const float*)d_in[4];
    const float* fcos = (const float*)d_in[7];
    const float* fsin = (const float*)d_in[8];
    float* out = (float*)d_out;

    __nv_bfloat16 *xh, *xl, *wqkvTh, *wqkvTl, *woTh, *woTl;
    __nv_bfloat16 *aoh, *aol, *pqh, *pql, *pkh, *pkl, *pvh, *pvl;
    cudaGetSymbolAddress((void**)&xh, g_xh);         cudaGetSymbolAddress((void**)&xl, g_xl);
    cudaGetSymbolAddress((void**)&wqkvTh, g_wqkvTh); cudaGetSymbolAddress((void**)&wqkvTl, g_wqkvTl);
    cudaGetSymbolAddress((void**)&woTh, g_woTh);     cudaGetSymbolAddress((void**)&woTl, g_woTl);
    cudaGetSymbolAddress((void**)&aoh, g_aoh);       cudaGetSymbolAddress((void**)&aol, g_aol);
    cudaGetSymbolAddress((void**)&pqh, g_qh);        cudaGetSymbolAddress((void**)&pql, g_ql);
    cudaGetSymbolAddress((void**)&pkh, g_kh);        cudaGetSymbolAddress((void**)&pkl, g_kl);
    cudaGetSymbolAddress((void**)&pvh, g_vh);        cudaGetSymbolAddress((void**)&pvl, g_vl);

    cudaFuncSetAttribute(gemm_mma,      cudaFuncAttributeMaxDynamicSharedMemorySize, GEMM_SMEM);
    cudaFuncSetAttribute(gemm_qkv_rope, cudaFuncAttributeMaxDynamicSharedMemorySize, GEMM_SMEM);
    cudaFuncSetAttribute(attn_mma,      cudaFuncAttributeMaxDynamicSharedMemorySize, ATT_SMEM);

    // 0: prep (x split + all weight transposes)
    prep_kernel<<<PREP_TOTAL, 256>>>(x, wq, wk, wv, wo, xh, xl, wqkvTh, wqkvTl, woTh, woTl);
    // 1: fused qkv projection + rope + split + relayout
    gemm_qkv_rope<<<dim3(NQKV / BN, MTOT / BM), 512, GEMM_SMEM>>>(
        xh, xl, wqkvTh, wqkvTl, fcos, fsin, pqh, pql, pkh, pkl, pvh, pvl);
    // 2: attention
    {
        dim3 grid(SEQ / 128, NH, BATCH);
        attn_mma<<<grid, 512, ATT_SMEM>>>(pqh, pql, pkh, pkl, pvh, pvl, aoh, aol);
    }
    // 3: output projection  <-- ncu capture slot
    gemm_mma<<<dim3(DIM / BN, MTOT / BM), 512, GEMM_SMEM>>>(aoh, aol, woTh, woTl, out, MTOT, DIM, NQ);
}

// round 14
// speedup vs baseline: 1.0588x; 1.0006x over previous
#include <cuda_runtime.h>
#include <cuda_bf16.h>
#include <cstdint>
#include <math.h>

#define BATCH 2
#define SEQ   2048
#define DIM   4096
#define NH    32
#define NKV   8
#define HD    128
#define NREP  4
#define MTOT  (BATCH*SEQ)   // 4096
#define NQ    (NH*HD)       // 4096
#define NKVD  (NKV*HD)      // 1024
#define NQKV  (NQ + 2*NKVD) // 6144

// -------- scratch (device globals) --------
__device__ __nv_bfloat16 g_xh[(size_t)MTOT*DIM],   g_xl[(size_t)MTOT*DIM];
__device__ __nv_bfloat16 g_wqkvTh[(size_t)NQKV*DIM], g_wqkvTl[(size_t)NQKV*DIM];
__device__ __nv_bfloat16 g_woTh[(size_t)DIM*NQ],   g_woTl[(size_t)DIM*NQ];
__device__ __nv_bfloat16 g_aoh[(size_t)MTOT*NQ],   g_aol[(size_t)MTOT*NQ];
__device__ __nv_bfloat16 g_qh[(size_t)MTOT*NQ],    g_ql[(size_t)MTOT*NQ];
__device__ __nv_bfloat16 g_kh[(size_t)MTOT*NKVD],  g_kl[(size_t)MTOT*NKVD];
__device__ __nv_bfloat16 g_vh[(size_t)MTOT*NKVD],  g_vl[(size_t)MTOT*NKVD];

// ============================================================
// PTX helpers
// ============================================================
__device__ __forceinline__ uint32_t smem_u32(const void* p) {
    uint32_t a;
    asm("{ .reg .u64 t; cvta.to.shared.u64 t, %1; cvt.u32.u64 %0, t; }" : "=r"(a) : "l"(p));
    return a;
}
__device__ __forceinline__ void cp16(uint32_t dst, const void* src) {
    asm volatile("cp.async.cg.shared.global [%0], [%1], 16;" :: "r"(dst), "l"(src));
}
#define CP_COMMIT()  asm volatile("cp.async.commit_group;")
#define CP_WAIT1()   asm volatile("cp.async.wait_group 1;")
#define CP_WAIT0()   asm volatile("cp.async.wait_group 0;")

__device__ __forceinline__ void ldsm4(uint32_t* r, uint32_t addr) {
    asm volatile("ldmatrix.sync.aligned.m8n8.x4.shared.b16 {%0,%1,%2,%3}, [%4];"
        : "=r"(r[0]), "=r"(r[1]), "=r"(r[2]), "=r"(r[3]) : "r"(addr));
}
__device__ __forceinline__ void ldsm4t(uint32_t* r, uint32_t addr) {
    asm volatile("ldmatrix.sync.aligned.m8n8.x4.trans.shared.b16 {%0,%1,%2,%3}, [%4];"
        : "=r"(r[0]), "=r"(r[1]), "=r"(r[2]), "=r"(r[3]) : "r"(addr));
}
__device__ __forceinline__ void mma16816(float* c, const uint32_t* a, const uint32_t* b) {
    asm volatile("mma.sync.aligned.m16n8k16.row.col.f32.bf16.bf16.f32 "
        "{%0,%1,%2,%3}, {%4,%5,%6,%7}, {%8,%9}, {%0,%1,%2,%3};"
        : "+f"(c[0]), "+f"(c[1]), "+f"(c[2]), "+f"(c[3])
        : "r"(a[0]), "r"(a[1]), "r"(a[2]), "r"(a[3]), "r"(b[0]), "r"(b[1]));
}
__device__ __forceinline__ uint32_t packbf(float a, float b) {
    __nv_bfloat162 v = __floats2bfloat162_rn(a, b);
    return *(uint32_t*)&v;
}

__device__ __forceinline__ uint32_t swz(int row, int seg) {     // 64B rows, 4 segs
    return (uint32_t)row * 64u + ((uint32_t)(seg ^ ((row >> 1) & 3)) << 4);
}
__device__ __forceinline__ uint32_t sw256(int row, int boff) {
    return (uint32_t)row * 256u + (uint32_t)(boff ^ ((row & 7) << 4));
}

// ============================================================
// GEMM mainloop (PROVEN 2-stage, BK=32): CTA 128x128, 512 threads
// (16 warps 4x4), warp tile 32x32, 2 barriers/chunk.
// ============================================================
#define BM 128
#define BN 128
#define BK 32
#define GOFF_AH 0u
#define GOFF_AL 8192u
#define GOFF_BH 16384u
#define GOFF_BL 24576u
#define GSTAGE  32768u
#define GEMM_SMEM (2*32768)

#define GEMM_MAINLOOP(Ah, Al, Bh, Bl, Kdim)                                     \
    extern __shared__ char smem[];                                              \
    const uint32_t sb = smem_u32(smem);                                         \
    const int t = threadIdx.x;                                                  \
    const int lane = t & 31, wid = t >> 5;                                      \
    const int m0 = blockIdx.y * BM, n0 = blockIdx.x * BN;                       \
    const int lrow = t >> 2, lseg = t & 3;                                      \
    const __nv_bfloat16* gAh = (Ah) + (size_t)(m0 + lrow) * (Kdim) + lseg * 8;  \
    const __nv_bfloat16* gAl = (Al) + (size_t)(m0 + lrow) * (Kdim) + lseg * 8;  \
    const __nv_bfloat16* gBh = (Bh) + (size_t)(n0 + lrow) * (Kdim) + lseg * 8;  \
    const __nv_bfloat16* gBl = (Bl) + (size_t)(n0 + lrow) * (Kdim) + lseg * 8;  \
    const uint32_t loff = swz(lrow, lseg);                                      \
    const int wm = (wid & 3) * 32;                                              \
    const int wn = (wid >> 2) * 32;                                             \
    const int arow = wm + (lane & 7) + ((lane >> 3) & 1) * 8;                   \
    const int aseg = lane >> 4;                                                 \
    const int brow = wn + (lane & 7) + ((lane >> 4) & 1) * 8;                   \
    const int bseg = (lane >> 3) & 1;                                           \
    float acc[2][4][4];                                                         \
    _Pragma("unroll")                                                           \
    for (int i = 0; i < 2; i++)                                                 \
        _Pragma("unroll")                                                       \
        for (int j = 0; j < 4; j++)                                             \
            _Pragma("unroll")                                                   \
            for (int v = 0; v < 4; v++) acc[i][j][v] = 0.f;                     \
    const int nch = (Kdim) / BK;                                                \
    {                                                                           \
        cp16(sb + GOFF_AH + loff, gAh); cp16(sb + GOFF_AL + loff, gAl);         \
        cp16(sb + GOFF_BH + loff, gBh); cp16(sb + GOFF_BL + loff, gBl);         \
        CP_COMMIT();                                                            \
        uint32_t b1 = sb + GSTAGE;                                              \
        cp16(b1 + GOFF_AH + loff, gAh + BK); cp16(b1 + GOFF_AL + loff, gAl + BK);\
        cp16(b1 + GOFF_BH + loff, gBh + BK); cp16(b1 + GOFF_BL + loff, gBl + BK);\
        CP_COMMIT();                                                            \
    }                                                                           \
    for (int ch = 0; ch < nch; ch++) {                                          \
        CP_WAIT1();                                                             \
        __syncthreads();                                                        \
        const uint32_t base = sb + (uint32_t)(ch & 1) * GSTAGE;                 \
        _Pragma("unroll")                                                       \
        for (int ks = 0; ks < 2; ks++) {                                        \
            uint32_t ah[2][4], al[2][4], bh[2][4], bl[2][4];                    \
            _Pragma("unroll")                                                   \
            for (int mt = 0; mt < 2; mt++) {                                    \
                uint32_t off = swz(arow + mt * 16, ks * 2 + aseg);              \
                ldsm4(ah[mt], base + GOFF_AH + off);                            \
                ldsm4(al[mt], base + GOFF_AL + off);                            \
            }                                                                   \
            _Pragma("unroll")                                                   \
            for (int np = 0; np < 2; np++) {                                    \
                uint32_t off = swz(brow + np * 16, ks * 2 + bseg);              \
                ldsm4(bh[np], base + GOFF_BH + off);                            \
                ldsm4(bl[np], base + GOFF_BL + off);                            \
            }                                                                   \
            _Pragma("unroll")                                                   \
            for (int np = 0; np < 2; np++)                                      \
                _Pragma("unroll")                                               \
                for (int mt = 0; mt < 2; mt++) {                                \
                    mma16816(acc[mt][np * 2],     ah[mt], bh[np] + 0);          \
                    mma16816(acc[mt][np * 2],     ah[mt], bl[np] + 0);          \
                    mma16816(acc[mt][np * 2],     al[mt], bh[np] + 0);          \
                    mma16816(acc[mt][np * 2 + 1], ah[mt], bh[np] + 2);          \
                    mma16816(acc[mt][np * 2 + 1], ah[mt], bl[np] + 2);          \
                    mma16816(acc[mt][np * 2 + 1], al[mt], bh[np] + 2);          \
                }                                                               \
        }                                                                       \
        __syncthreads();                                                        \
        if (ch + 2 < nch) {                                                     \
            int k0 = (ch + 2) * BK;                                             \
            cp16(base + GOFF_AH + loff, gAh + k0); cp16(base + GOFF_AL + loff, gAl + k0);\
            cp16(base + GOFF_BH + loff, gBh + k0); cp16(base + GOFF_BL + loff, gBl + k0);\
        }                                                                       \
        CP_COMMIT();                                                            \
    }

// ---- plain GEMM (fp32 C out) — wo projection ----
__global__ void __launch_bounds__(512, 1) gemm_mma(
    const __nv_bfloat16* __restrict__ Ah, const __nv_bfloat16* __restrict__ Al,
    const __nv_bfloat16* __restrict__ Bh, const __nv_bfloat16* __restrict__ Bl,
    float* __restrict__ C, int M, int N, int K)
{
    GEMM_MAINLOOP(Ah, Al, Bh, Bl, K)
    #pragma unroll
    for (int mt = 0; mt < 2; mt++) {
        int r0 = m0 + wm + mt * 16 + (lane >> 2);
        #pragma unroll
        for (int nt = 0; nt < 4; nt++) {
            int c0 = n0 + wn + nt * 8 + (lane & 3) * 2;
            *(float2*)(C + (size_t)r0 * N + c0)       = make_float2(acc[mt][nt][0], acc[mt][nt][1]);
            *(float2*)(C + (size_t)(r0 + 8) * N + c0) = make_float2(acc[mt][nt][2], acc[mt][nt][3]);
        }
    }
}

// ---- qkv GEMM + fused RoPE/split/relayout; cos/sin staged in smem ----
__global__ void __launch_bounds__(512, 1) gemm_qkv_rope(
    const __nv_bfloat16* __restrict__ Ah, const __nv_bfloat16* __restrict__ Al,
    const __nv_bfloat16* __restrict__ Bh, const __nv_bfloat16* __restrict__ Bl,
    const float* __restrict__ fcos, const float* __restrict__ fsin,
    __nv_bfloat16* __restrict__ qh, __nv_bfloat16* __restrict__ ql,
    __nv_bfloat16* __restrict__ kh, __nv_bfloat16* __restrict__ kl,
    __nv_bfloat16* __restrict__ vh, __nv_bfloat16* __restrict__ vl)
{
    GEMM_MAINLOOP(Ah, Al, Bh, Bl, DIM)

    // ---- CTA-uniform region config ----
    __nv_bfloat16 *dh, *dl;
    int do_rope;
    float scale;
    uint32_t headSeqBase;
    if (n0 < NQ) {
        dh = qh; dl = ql; do_rope = 1; scale = 0.08838834764831845f;
        headSeqBase = (uint32_t)(n0 >> 7) * SEQ;
    } else if (n0 < NQ + NKVD) {
        dh = kh; dl = kl; do_rope = 1; scale = 1.0f;
        headSeqBase = (uint32_t)((n0 - NQ) >> 7) * SEQ;
    } else {
        dh = vh; dl = vl; do_rope = 0; scale = 1.0f;
        headSeqBase = (uint32_t)((n0 - NQ - NKVD) >> 7) * SEQ;
    }
    const uint32_t batchStride = (n0 < NQ) ? (uint32_t)NH * SEQ : (uint32_t)NKV * SEQ;
    const int s0 = m0 & (SEQ - 1);        // 128-row tile sits in one batch

    // ---- stage cos/sin (128 rows x 64) into dead stage smem, swizzled ----
    // phys float4 index: srel*16 + (g ^ (srel & 7)),  g = logical group (f4 idx in row)
    float* smf = (float*)smem;            // cos at [0, 8192) floats, sin at [8192, 16384)
    if (do_rope) {
        const float4* c4 = (const float4*)(fcos + (size_t)s0 * (HD / 2));
        const float4* s4 = (const float4*)(fsin + (size_t)s0 * (HD / 2));
        float4* smf4 = (float4*)smem;
        #pragma unroll
        for (int i = t; i < 2048; i += 512) {
            int srel = i >> 4, g = i & 15;
            int phys = srel * 16 + (g ^ (srel & 7));
            smf4[phys]        = c4[i];
            smf4[2048 + phys] = s4[i];
        }
        __syncthreads();
    }

    #pragma unroll
    for (int mt = 0; mt < 2; mt++) {
        int rr = wm + mt * 16 + (lane >> 2);            // row in CTA tile (mod the +8 half)
        #pragma unroll
        for (int half = 0; half < 2; half++) {
            int srel = rr + half * 8;                   // 0..127
            int r = m0 + srel;
            uint32_t bb = (uint32_t)r >> 11;
            uint32_t s  = (uint32_t)(s0 + srel);
            uint32_t rowBase = (bb * batchStride + headSeqBase + s) * HD;
            #pragma unroll
            for (int nt = 0; nt < 4; nt++) {
                int d = wn + nt * 8 + (lane & 3) * 2;   // 0..127, even
                float f0 = acc[mt][nt][half * 2];
                float f1 = acc[mt][nt][half * 2 + 1];
                float outr, outi;
                if (do_rope) {
                    int g = (wn >> 3) + nt;             // logical f4 group of d>>1
                    int pf = srel * 64 + (((g) ^ (srel & 7)) << 2) + (lane & 3);
                    float c = smf[pf], sn = smf[8192 + pf];
                    outr = (f0 * c - f1 * sn) * scale;
                    outi = (f0 * sn + f1 * c) * scale;
                } else {
                    outr = f0; outi = f1;
                }
                uint32_t hp = packbf(outr, outi);
                __nv_bfloat162 hb = *(__nv_bfloat162*)&hp;
                uint32_t lo = packbf(outr - __bfloat162float(hb.x),
                                     outi - __bfloat162float(hb.y));
                *(uint32_t*)(dh + rowBase + d) = hp;
                *(uint32_t*)(dl + rowBase + d) = lo;
            }
        }
    }
}

// ============================================================
// prep: fused x-split + qkv weight transpose + wo transpose (one launch)
// ============================================================
#define PREP_SPLIT_BLKS 32768
#define PREP_QKV_BLKS   24576
#define PREP_TOTAL      (PREP_SPLIT_BLKS + PREP_QKV_BLKS + 16384)

__global__ void __launch_bounds__(256) prep_kernel(
    const float* __restrict__ x,  const float* __restrict__ Wq,
    const float* __restrict__ Wk, const float* __restrict__ Wv,
    const float* __restrict__ Wo,
    __nv_bfloat16* __restrict__ xh,  __nv_bfloat16* __restrict__ xl,
    __nv_bfloat16* __restrict__ qkvTh, __nv_bfloat16* __restrict__ qkvTl,
    __nv_bfloat16* __restrict__ woTh,  __nv_bfloat16* __restrict__ woTl)
{
    __shared__ float tile[32][33];
    int bid = blockIdx.x, t = threadIdx.x;

    if (bid < PREP_SPLIT_BLKS) {
        int i = bid * 256 + t;
        float2 v = ((const float2*)x)[i];
        __nv_bfloat16 hx = __float2bfloat16(v.x), hy = __float2bfloat16(v.y);
        ((__nv_bfloat162*)xh)[i] = __halves2bfloat162(hx, hy);
        ((__nv_bfloat162*)xl)[i] = __halves2bfloat162(
            __float2bfloat16(v.x - __bfloat162float(hx)),
            __float2bfloat16(v.y - __bfloat162float(hy)));
        return;
    }

    int tx = t & 31, ty = t >> 5;
    const float* src; __nv_bfloat16 *Th, *Tl;
    int srcN, outK, nsrc, rowoff, by;
    if (bid < PREP_SPLIT_BLKS + PREP_QKV_BLKS) {
        int b2 = bid - PREP_SPLIT_BLKS;
        int bx = b2 % 192; by = b2 / 192;
        Th = qkvTh; Tl = qkvTl; outK = DIM;
        if (bx < 128)      { src = Wq; srcN = NQ;   nsrc = bx * 32;         rowoff = 0;    }
        else if (bx < 160) { src = Wk; srcN = NKVD; nsrc = (bx - 128) * 32; rowoff = NQ;   }
        else               { src = Wv; srcN = NKVD; nsrc = (bx - 160) * 32; rowoff = NQ + NKVD; }
    } else {
        int b2 = bid - PREP_SPLIT_BLKS - PREP_QKV_BLKS;
        int bx = b2 % 128; by = b2 / 128;
        Th = woTh; Tl = woTl; outK = NQ;
        src = Wo; srcN = DIM; nsrc = bx * 32; rowoff = 0;
    }

    int n = nsrc + tx;
    #pragma unroll
    for (int j = 0; j < 4; j++) {
        int k = by * 32 + ty + j * 8;
        tile[ty + j * 8][tx] = src[(size_t)k * srcN + n];
    }
    __syncthreads();
    int k2 = by * 32 + tx;
    #pragma unroll
    for (int j = 0; j < 4; j++) {
        int n2 = rowoff + nsrc + ty + j * 8;
        float v = tile[tx][ty + j * 8];
        __nv_bfloat16 h = __float2bfloat16(v);
        Th[(size_t)n2 * outK + k2] = h;
        Tl[(size_t)n2 * outK + k2] = __float2bfloat16(v - __bfloat162float(h));
    }
}

// ============================================================
// flash attention v4 (R11 winner, byte-identical)
// ============================================================
#define NTILE (SEQ/64)
#define AKV_STG 65536u
#define AQ_OFF  131072u
#define ARED_OFF 196608u
#define ATT_SMEM 198656

__global__ void __launch_bounds__(512, 1) attn_mma(
    const __nv_bfloat16* __restrict__ qh, const __nv_bfloat16* __restrict__ ql,
    const __nv_bfloat16* __restrict__ kh, const __nv_bfloat16* __restrict__ kl,
    const __nv_bfloat16* __restrict__ vh, const __nv_bfloat16* __restrict__ vl,
    __nv_bfloat16* __restrict__ outh, __nv_bfloat16* __restrict__ outl)
{
    extern __shared__ char sm[];
    const uint32_t sb = smem_u32(sm);
    const int t = threadIdx.x, lane = t & 31, w = t >> 5;
    const int wm = w & 7, wn = w >> 3;
    const int qt = blockIdx.x, h = blockIdx.y, b = blockIdx.z;
    const int kvh = h >> 2;

    const __nv_bfloat16* qhg = qh + ((size_t)(b * NH + h) * SEQ + qt * 128) * HD;
    const __nv_bfloat16* qlg = ql + ((size_t)(b * NH + h) * SEQ + qt * 128) * HD;
    const size_t kvb = (size_t)(b * NKV + kvh) * SEQ * HD;

    {
        int r = t >> 2, seg = t & 3;
        #pragma unroll
        for (int j = 0; j < 4; j++) {
            int boff = seg * 64 + j * 16;
            uint4 a = *(const uint4*)(qhg + (size_t)r * HD + boff / 2);
            *(uint4*)(sm + AQ_OFF + sw256(r, boff)) = a;
            uint4 c = *(const uint4*)(qlg + (size_t)r * HD + boff / 2);
            *(uint4*)(sm + AQ_OFF + 32768u + sw256(r, boff)) = c;
        }
    }

    const int lrow = t >> 3, lsg = t & 7;
#define LOAD_KV(kt, stg) do {                                                   \
    uint32_t bufb = sb + (uint32_t)(stg) * AKV_STG;                             \
    size_t grow = kvb + ((size_t)(kt) * 64 + lrow) * HD;                        \
    _Pragma("unroll")                                                           \
    for (int j = 0; j < 2; j++) {                                               \
        int boff = lsg * 32 + j * 16;                                           \
        uint32_t sd = sw256(lrow, boff);                                        \
        cp16(bufb + sd,          kh + grow + boff / 2);                         \
        cp16(bufb + 16384u + sd, kl + grow + boff / 2);                         \
        cp16(bufb + 32768u + sd, vh + grow + boff / 2);                         \
        cp16(bufb + 49152u + sd, vl + grow + boff / 2);                         \
    }                                                                           \
} while (0)

    LOAD_KV(0, 0); CP_COMMIT();

    float lp[2] = {0.f, 0.f};
    float oacc[16][4];
    #pragma unroll
    for (int i = 0; i < 16; i++)
        #pragma unroll
        for (int j = 0; j < 4; j++) oacc[i][j] = 0.f;

    const int row1 = wm * 16 + (lane >> 2);
    const int row2 = row1 + 8;
    const int qar = wm * 16 + (lane & 7) + ((lane >> 3) & 1) * 8;
    const int qab = (lane >> 4) * 16;

    for (int kt = 0; kt < NTILE; kt++) {
        if (kt + 1 < NTILE) { LOAD_KV(kt + 1, (kt + 1) & 1); CP_COMMIT(); CP_WAIT1(); }
        else                { CP_WAIT0(); }
        __syncthreads();
        const uint32_t kbuf = sb + (uint32_t)(kt & 1) * AKV_STG;
        const uint32_t vbuf = kbuf + 32768u;

        float sacc[4][4];
        #pragma unroll
        for (int i = 0; i < 4; i++)
            #pragma unroll
            for (int j = 0; j < 4; j++) sacc[i][j] = 0.f;
        {
            int br = wn * 32 + (lane & 7) + (lane >> 4) * 8;
            int bb0 = ((lane >> 3) & 1) * 16;
            #pragma unroll
            for (int ks = 0; ks < 8; ks++) {
                uint32_t qfh[4], qfl[4];
                uint32_t qoff = sw256(qar, ks * 32 + qab);
                ldsm4(qfh, sb + AQ_OFF + qoff);
                ldsm4(qfl, sb + AQ_OFF + 32768u + qoff);
                #pragma unroll
                for (int np = 0; np < 2; np++) {
                    uint32_t bh[4], bl[4];
                    uint32_t off = sw256(br + np * 16, ks * 32 + bb0);
                    ldsm4(bh, kbuf + off);
                    ldsm4(bl, kbuf + 16384u + off);
                    mma16816(sacc[np * 2],     qfh, bh + 0);
                    mma16816(sacc[np * 2],     qfh, bl + 0);
                    mma16816(sacc[np * 2],     qfl, bh + 0);
                    mma16816(sacc[np * 2 + 1], qfh, bh + 2);
                    mma16816(sacc[np * 2 + 1], qfh, bl + 2);
                    mma16816(sacc[np * 2 + 1], qfl, bh + 2);
                }
            }
        }

        float p[4][4];
        #pragma unroll
        for (int nt = 0; nt < 4; nt++) {
            p[nt][0] = __expf(sacc[nt][0]);
            p[nt][1] = __expf(sacc[nt][1]);
            p[nt][2] = __expf(sacc[nt][2]);
            p[nt][3] = __expf(sacc[nt][3]);
            lp[0] += p[nt][0] + p[nt][1];
            lp[1] += p[nt][2] + p[nt][3];
        }

        {
            int vr0 = (lane & 7) + ((lane >> 3) & 1) * 8;
            int vc0 = (lane >> 4) * 16;
            #pragma unroll
            for (int kb = 0; kb < 2; kb++) {
                uint32_t pfh[4], pfl[4];
                {
                    const float* t0 = p[kb * 2];
                    const float* t1 = p[kb * 2 + 1];
                    pfh[0] = packbf(t0[0], t0[1]);
                    pfh[1] = packbf(t0[2], t0[3]);
                    pfh[2] = packbf(t1[0], t1[1]);
                    pfh[3] = packbf(t1[2], t1[3]);
                    __nv_bfloat162 h0 = *(__nv_bfloat162*)&pfh[0];
                    __nv_bfloat162 h1 = *(__nv_bfloat162*)&pfh[1];
                    __nv_bfloat162 h2 = *(__nv_bfloat162*)&pfh[2];
                    __nv_bfloat162 h3 = *(__nv_bfloat162*)&pfh[3];
                    pfl[0] = packbf(t0[0] - __bfloat162float(h0.x), t0[1] - __bfloat162float(h0.y));
                    pfl[1] = packbf(t0[2] - __bfloat162float(h1.x), t0[3] - __bfloat162float(h1.y));
                    pfl[2] = packbf(t1[0] - __bfloat162float(h2.x), t1[1] - __bfloat162float(h2.y));
                    pfl[3] = packbf(t1[2] - __bfloat162float(h3.x), t1[3] - __bfloat162float(h3.y));
                }
                int vrow = wn * 32 + kb * 16 + vr0;
                #pragma unroll
                for (int db = 0; db < 8; db++) {
                    uint32_t wh[4], wl[4];
                    uint32_t off = sw256(vrow, db * 32 + vc0);
                    ldsm4t(wh, vbuf + off);
                    ldsm4t(wl, vbuf + 16384u + off);
                    mma16816(oacc[db * 2],     pfh, wh + 0);
                    mma16816(oacc[db * 2],     pfh, wl + 0);
                    mma16816(oacc[db * 2],     pfl, wh + 0);
                    mma16816(oacc[db * 2 + 1], pfh, wh + 2);
                    mma16816(oacc[db * 2 + 1], pfh, wl + 2);
                    mma16816(oacc[db * 2 + 1], pfl, wh + 2);
                }
            }
        }
        __syncthreads();
    }

    {
        lp[0] += __shfl_xor_sync(0xffffffffu, lp[0], 1);
        lp[0] += __shfl_xor_sync(0xffffffffu, lp[0], 2);
        lp[1] += __shfl_xor_sync(0xffffffffu, lp[1], 1);
        lp[1] += __shfl_xor_sync(0xffffffffu, lp[1], 2);
        float* reds = (float*)(sm + ARED_OFF);
        if ((lane & 3) == 0) {
            reds[wn * 128 + row1] = lp[0];
            reds[wn * 128 + row2] = lp[1];
        }
        float* ox = (float*)sm;
        if (wn == 1) {
            #pragma unroll
            for (int nt = 0; nt < 16; nt++) {
                int c0 = nt * 8 + (lane & 3) * 2;
                *(float2*)(ox + (size_t)row1 * 128 + c0) = make_float2(oacc[nt][0], oacc[nt][1]);
                *(float2*)(ox + (size_t)row2 * 128 + c0) = make_float2(oacc[nt][2], oacc[nt][3]);
            }
        }
        __syncthreads();
        if (wn == 0) {
            float inv1 = 1.f / (reds[row1] + reds[128 + row1]);
            float inv2 = 1.f / (reds[row2] + reds[128 + row2]);
            int rg1 = qt * 128 + row1, rg2 = qt * 128 + row2;
            size_t b1 = ((size_t)(b * SEQ + rg1) * NH + h) * HD;
            size_t b2 = ((size_t)(b * SEQ + rg2) * NH + h) * HD;
            #pragma unroll
            for (int nt = 0; nt < 16; nt++) {
                int c0 = nt * 8 + (lane & 3) * 2;
                float2 x1 = *(float2*)(ox + (size_t)row1 * 128 + c0);
                float2 x2 = *(float2*)(ox + (size_t)row2 * 128 + c0);
                float f0 = (oacc[nt][0] + x1.x) * inv1;
                float f1 = (oacc[nt][1] + x1.y) * inv1;
                float f2 = (oacc[nt][2] + x2.x) * inv2;
                float f3 = (oacc[nt][3] + x2.y) * inv2;
                uint32_t h01 = packbf(f0, f1), h23 = packbf(f2, f3);
                __nv_bfloat162 bb01 = *(__nv_bfloat162*)&h01;
                __nv_bfloat162 bb23 = *(__nv_bfloat162*)&h23;
                uint32_t l01 = packbf(f0 - __bfloat162float(bb01.x), f1 - __bfloat162float(bb01.y));
                uint32_t l23 = packbf(f2 - __bfloat162float(bb23.x), f3 - __bfloat162float(bb23.y));
                *(uint32_t*)(outh + b1 + c0) = h01;
                *(uint32_t*)(outh + b2 + c0) = h23;
                *(uint32_t*)(outl + b1 + c0) = l01;
                *(uint32_t*)(outl + b2 + c0) = l23;
            }
        }
    }
#undef LOAD_KV
}

// ============================================================
// launch  (0 prep, 1 gemm_qkv_rope, 2 attn, 3 gemm_wo <- ncu slot)
// ============================================================
extern "C" void kernel_launch(void* const* d_in, const int* in_sizes, int n_in,
                              void* d_out, int out_size)
{
    const float* x  = (const float*)d_in[0];
    const float* wq = (const float*)d_in[1];
    const float* wk = (const float*)d_in[2];
    const float* wv = (const float*)d_in[3];
    const float* wo = (const float*)d_in[4];
    const float* fcos = (const float*)d_in[7];
    const float* fsin = (const float*)d_in[8];
    float* out = (float*)d_out;

    __nv_bfloat16 *xh, *xl, *wqkvTh, *wqkvTl, *woTh, *woTl;
    __nv_bfloat16 *aoh, *aol, *pqh, *pql, *pkh, *pkl, *pvh, *pvl;
    cudaGetSymbolAddress((void**)&xh, g_xh);         cudaGetSymbolAddress((void**)&xl, g_xl);
    cudaGetSymbolAddress((void**)&wqkvTh, g_wqkvTh); cudaGetSymbolAddress((void**)&wqkvTl, g_wqkvTl);
    cudaGetSymbolAddress((void**)&woTh, g_woTh);     cudaGetSymbolAddress((void**)&woTl, g_woTl);
    cudaGetSymbolAddress((void**)&aoh, g_aoh);       cudaGetSymbolAddress((void**)&aol, g_aol);
    cudaGetSymbolAddress((void**)&pqh, g_qh);        cudaGetSymbolAddress((void**)&pql, g_ql);
    cudaGetSymbolAddress((void**)&pkh, g_kh);        cudaGetSymbolAddress((void**)&pkl, g_kl);
    cudaGetSymbolAddress((void**)&pvh, g_vh);        cudaGetSymbolAddress((void**)&pvl, g_vl);

    cudaFuncSetAttribute(gemm_mma,      cudaFuncAttributeMaxDynamicSharedMemorySize, GEMM_SMEM);
    cudaFuncSetAttribute(gemm_qkv_rope, cudaFuncAttributeMaxDynamicSharedMemorySize, GEMM_SMEM);
    cudaFuncSetAttribute(attn_mma,      cudaFuncAttributeMaxDynamicSharedMemorySize, ATT_SMEM);

    // 0: prep (x split + all weight transposes)
    prep_kernel<<<PREP_TOTAL, 256>>>(x, wq, wk, wv, wo, xh, xl, wqkvTh, wqkvTl, woTh, woTl);
    // 1: fused qkv projection + rope + split + relayout
    gemm_qkv_rope<<<dim3(NQKV / BN, MTOT / BM), 512, GEMM_SMEM>>>(
        xh, xl, wqkvTh, wqkvTl, fcos, fsin, pqh, pql, pkh, pkl, pvh, pvl);
    // 2: attention
    {
        dim3 grid(SEQ / 128, NH, BATCH);
        attn_mma<<<grid, 512, ATT_SMEM>>>(pqh, pql, pkh, pkl, pvh, pvl, aoh, aol);
    }
    // 3: output projection  <-- ncu capture slot
    gemm_mma<<<dim3(DIM / BN, MTOT / BM), 512, GEMM_SMEM>>>(aoh, aol, woTh, woTl, out, MTOT, DIM, NQ);
}

// round 16
// speedup vs baseline: 1.0639x; 1.0048x over previous
#include <cuda_runtime.h>
#include <cuda_bf16.h>
#include <cstdint>
#include <math.h>

#define BATCH 2
#define SEQ   2048
#define DIM   4096
#define NH    32
#define NKV   8
#define HD    128
#define NREP  4
#define MTOT  (BATCH*SEQ)   // 4096
#define NQ    (NH*HD)       // 4096
#define NKVD  (NKV*HD)      // 1024
#define NQKV  (NQ + 2*NKVD) // 6144

// -------- scratch (device globals) --------
__device__ float g_qkv[(size_t)MTOT*NQKV];

__device__ __nv_bfloat16 g_xh[(size_t)MTOT*DIM],   g_xl[(size_t)MTOT*DIM];
__device__ __nv_bfloat16 g_wqkvTh[(size_t)NQKV*DIM], g_wqkvTl[(size_t)NQKV*DIM];
__device__ __nv_bfloat16 g_woTh[(size_t)DIM*NQ],   g_woTl[(size_t)DIM*NQ];
__device__ __nv_bfloat16 g_aoh[(size_t)MTOT*NQ],   g_aol[(size_t)MTOT*NQ];
__device__ __nv_bfloat16 g_qh[(size_t)MTOT*NQ],    g_ql[(size_t)MTOT*NQ];
__device__ __nv_bfloat16 g_kh[(size_t)MTOT*NKVD],  g_kl[(size_t)MTOT*NKVD];
__device__ __nv_bfloat16 g_vh[(size_t)MTOT*NKVD],  g_vl[(size_t)MTOT*NKVD];

// ============================================================
// PTX helpers
// ============================================================
__device__ __forceinline__ uint32_t smem_u32(const void* p) {
    uint32_t a;
    asm("{ .reg .u64 t; cvta.to.shared.u64 t, %1; cvt.u32.u64 %0, t; }" : "=r"(a) : "l"(p));
    return a;
}
__device__ __forceinline__ void cp16(uint32_t dst, const void* src) {
    asm volatile("cp.async.cg.shared.global [%0], [%1], 16;" :: "r"(dst), "l"(src));
}
#define CP_COMMIT()  asm volatile("cp.async.commit_group;")
#define CP_WAIT1()   asm volatile("cp.async.wait_group 1;")
#define CP_WAIT0()   asm volatile("cp.async.wait_group 0;")

__device__ __forceinline__ void ldsm4(uint32_t* r, uint32_t addr) {
    asm volatile("ldmatrix.sync.aligned.m8n8.x4.shared.b16 {%0,%1,%2,%3}, [%4];"
        : "=r"(r[0]), "=r"(r[1]), "=r"(r[2]), "=r"(r[3]) : "r"(addr));
}
__device__ __forceinline__ void ldsm4t(uint32_t* r, uint32_t addr) {
    asm volatile("ldmatrix.sync.aligned.m8n8.x4.trans.shared.b16 {%0,%1,%2,%3}, [%4];"
        : "=r"(r[0]), "=r"(r[1]), "=r"(r[2]), "=r"(r[3]) : "r"(addr));
}
__device__ __forceinline__ void mma16816(float* c, const uint32_t* a, const uint32_t* b) {
    asm volatile("mma.sync.aligned.m16n8k16.row.col.f32.bf16.bf16.f32 "
        "{%0,%1,%2,%3}, {%4,%5,%6,%7}, {%8,%9}, {%0,%1,%2,%3};"
        : "+f"(c[0]), "+f"(c[1]), "+f"(c[2]), "+f"(c[3])
        : "r"(a[0]), "r"(a[1]), "r"(a[2]), "r"(a[3]), "r"(b[0]), "r"(b[1]));
}
__device__ __forceinline__ uint32_t packbf(float a, float b) {
    __nv_bfloat162 v = __floats2bfloat162_rn(a, b);
    return *(uint32_t*)&v;
}

__device__ __forceinline__ uint32_t swz(int row, int seg) {     // 64B rows, 4 segs
    return (uint32_t)row * 64u + ((uint32_t)(seg ^ ((row >> 1) & 3)) << 4);
}
__device__ __forceinline__ uint32_t sw256(int row, int boff) {
    return (uint32_t)row * 256u + (uint32_t)(boff ^ ((row & 7) << 4));
}

// ============================================================
// split-bf16 GEMM (proven 2-stage BK=32): CTA 128x128, 512 threads
// (16 warps 4x4), warp tile 32x32.  Byte-identical to R11.
// ============================================================
#define BM 128
#define BN 128
#define BK 32
#define GOFF_AH 0u
#define GOFF_AL 8192u
#define GOFF_BH 16384u
#define GOFF_BL 24576u
#define GSTAGE  32768u
#define GEMM_SMEM (2*32768)

__global__ void __launch_bounds__(512, 1) gemm_mma(
    const __nv_bfloat16* __restrict__ Ah, const __nv_bfloat16* __restrict__ Al,
    const __nv_bfloat16* __restrict__ Bh, const __nv_bfloat16* __restrict__ Bl,
    float* __restrict__ C, int M, int N, int K)
{
    extern __shared__ char smem[];
    const uint32_t sb = smem_u32(smem);
    const int t = threadIdx.x;
    const int lane = t & 31, wid = t >> 5;
    const int m0 = blockIdx.y * BM, n0 = blockIdx.x * BN;

    const int lrow = t >> 2, lseg = t & 3;
    const __nv_bfloat16* gAh = Ah + (size_t)(m0 + lrow) * K + lseg * 8;
    const __nv_bfloat16* gAl = Al + (size_t)(m0 + lrow) * K + lseg * 8;
    const __nv_bfloat16* gBh = Bh + (size_t)(n0 + lrow) * K + lseg * 8;
    const __nv_bfloat16* gBl = Bl + (size_t)(n0 + lrow) * K + lseg * 8;
    const uint32_t loff = swz(lrow, lseg);

#define LOAD_CHUNK(k0, base) do {                   \
    cp16((base) + GOFF_AH + loff, gAh + (k0));      \
    cp16((base) + GOFF_AL + loff, gAl + (k0));      \
    cp16((base) + GOFF_BH + loff, gBh + (k0));      \
    cp16((base) + GOFF_BL + loff, gBl + (k0));      \
} while (0)

    const int wm = (wid & 3) * 32;
    const int wn = (wid >> 2) * 32;
    const int arow = wm + (lane & 7) + ((lane >> 3) & 1) * 8;
    const int aseg = lane >> 4;
    const int brow = wn + (lane & 7) + ((lane >> 4) & 1) * 8;
    const int bseg = (lane >> 3) & 1;

    float acc[2][4][4];
    #pragma unroll
    for (int i = 0; i < 2; i++)
        #pragma unroll
        for (int j = 0; j < 4; j++)
            #pragma unroll
            for (int v = 0; v < 4; v++) acc[i][j][v] = 0.f;

    const int nch = K / BK;
    LOAD_CHUNK(0, sb);            CP_COMMIT();
    LOAD_CHUNK(BK, sb + GSTAGE);  CP_COMMIT();

    for (int ch = 0; ch < nch; ch++) {
        CP_WAIT1();
        __syncthreads();
        const uint32_t base = sb + (uint32_t)(ch & 1) * GSTAGE;

        #pragma unroll
        for (int ks = 0; ks < 2; ks++) {
            uint32_t ah[2][4], al[2][4], bh[2][4], bl[2][4];
            #pragma unroll
            for (int mt = 0; mt < 2; mt++) {
                uint32_t off = swz(arow + mt * 16, ks * 2 + aseg);
                ldsm4(ah[mt], base + GOFF_AH + off);
                ldsm4(al[mt], base + GOFF_AL + off);
            }
            #pragma unroll
            for (int np = 0; np < 2; np++) {
                uint32_t off = swz(brow + np * 16, ks * 2 + bseg);
                ldsm4(bh[np], base + GOFF_BH + off);
                ldsm4(bl[np], base + GOFF_BL + off);
            }
            #pragma unroll
            for (int np = 0; np < 2; np++)
                #pragma unroll
                for (int mt = 0; mt < 2; mt++) {
                    mma16816(acc[mt][np * 2],     ah[mt], bh[np] + 0);
                    mma16816(acc[mt][np * 2],     ah[mt], bl[np] + 0);
                    mma16816(acc[mt][np * 2],     al[mt], bh[np] + 0);
                    mma16816(acc[mt][np * 2 + 1], ah[mt], bh[np] + 2);
                    mma16816(acc[mt][np * 2 + 1], ah[mt], bl[np] + 2);
                    mma16816(acc[mt][np * 2 + 1], al[mt], bh[np] + 2);
                }
        }
        __syncthreads();
        if (ch + 2 < nch) LOAD_CHUNK((ch + 2) * BK, base);
        CP_COMMIT();
    }

    #pragma unroll
    for (int mt = 0; mt < 2; mt++) {
        int r0 = m0 + wm + mt * 16 + (lane >> 2);
        #pragma unroll
        for (int nt = 0; nt < 4; nt++) {
            int c0 = n0 + wn + nt * 8 + (lane & 3) * 2;
            *(float2*)(C + (size_t)r0 * N + c0)       = make_float2(acc[mt][nt][0], acc[mt][nt][1]);
            *(float2*)(C + (size_t)(r0 + 8) * N + c0) = make_float2(acc[mt][nt][2], acc[mt][nt][3]);
        }
    }
#undef LOAD_CHUNK
}

// ============================================================
// prep: fused x-split + qkv weight transpose + wo transpose (one launch)
// ============================================================
#define PREP_SPLIT_BLKS 32768
#define PREP_QKV_BLKS   24576
#define PREP_TOTAL      (PREP_SPLIT_BLKS + PREP_QKV_BLKS + 16384)

__global__ void __launch_bounds__(256) prep_kernel(
    const float* __restrict__ x,  const float* __restrict__ Wq,
    const float* __restrict__ Wk, const float* __restrict__ Wv,
    const float* __restrict__ Wo,
    __nv_bfloat16* __restrict__ xh,  __nv_bfloat16* __restrict__ xl,
    __nv_bfloat16* __restrict__ qkvTh, __nv_bfloat16* __restrict__ qkvTl,
    __nv_bfloat16* __restrict__ woTh,  __nv_bfloat16* __restrict__ woTl)
{
    __shared__ float tile[32][33];
    int bid = blockIdx.x, t = threadIdx.x;

    if (bid < PREP_SPLIT_BLKS) {
        int i = bid * 256 + t;
        float2 v = ((const float2*)x)[i];
        __nv_bfloat16 hx = __float2bfloat16(v.x), hy = __float2bfloat16(v.y);
        ((__nv_bfloat162*)xh)[i] = __halves2bfloat162(hx, hy);
        ((__nv_bfloat162*)xl)[i] = __halves2bfloat162(
            __float2bfloat16(v.x - __bfloat162float(hx)),
            __float2bfloat16(v.y - __bfloat162float(hy)));
        return;
    }

    int tx = t & 31, ty = t >> 5;
    const float* src; __nv_bfloat16 *Th, *Tl;
    int srcN, outK, nsrc, rowoff, by;
    if (bid < PREP_SPLIT_BLKS + PREP_QKV_BLKS) {
        int b2 = bid - PREP_SPLIT_BLKS;
        int bx = b2 % 192; by = b2 / 192;
        Th = qkvTh; Tl = qkvTl; outK = DIM;
        if (bx < 128)      { src = Wq; srcN = NQ;   nsrc = bx * 32;         rowoff = 0;    }
        else if (bx < 160) { src = Wk; srcN = NKVD; nsrc = (bx - 128) * 32; rowoff = NQ;   }
        else               { src = Wv; srcN = NKVD; nsrc = (bx - 160) * 32; rowoff = NQ + NKVD; }
    } else {
        int b2 = bid - PREP_SPLIT_BLKS - PREP_QKV_BLKS;
        int bx = b2 % 128; by = b2 / 128;
        Th = woTh; Tl = woTl; outK = NQ;
        src = Wo; srcN = DIM; nsrc = bx * 32; rowoff = 0;
    }

    int n = nsrc + tx;
    #pragma unroll
    for (int j = 0; j < 4; j++) {
        int k = by * 32 + ty + j * 8;
        tile[ty + j * 8][tx] = src[(size_t)k * srcN + n];
    }
    __syncthreads();
    int k2 = by * 32 + tx;
    #pragma unroll
    for (int j = 0; j < 4; j++) {
        int n2 = rowoff + nsrc + ty + j * 8;
        float v = tile[tx][ty + j * 8];
        __nv_bfloat16 h = __float2bfloat16(v);
        Th[(size_t)n2 * outK + k2] = h;
        Tl[(size_t)n2 * outK + k2] = __float2bfloat16(v - __bfloat162float(h));
    }
}

// ============================================================
// rope + layout change + hi/lo split — float4 (2 complex pairs)/thread
// ============================================================
__global__ void rope_split(const float* __restrict__ qkv,
                           const float* __restrict__ cos_, const float* __restrict__ sin_,
                           __nv_bfloat16* qh, __nv_bfloat16* ql,
                           __nv_bfloat16* kh, __nv_bfloat16* kl,
                           __nv_bfloat16* vh, __nv_bfloat16* vl)
{
    const int HD4 = HD / 4;                       // float4 groups per head
    const int nq4 = BATCH * SEQ * NH * HD4;
    const int nk4 = BATCH * SEQ * NKV * HD4;
    const float qscale = 0.08838834764831845f;
    int idx = blockIdx.x * blockDim.x + threadIdx.x;
    if (idx >= nq4 + 2 * nk4) return;

    int j = idx, isq = 1, isv = 0;
    const int nh = (idx < nq4) ? NH : NKV;
    int coloff = 0;
    __nv_bfloat16 *dh, *dl;
    if (idx < nq4) { dh = qh; dl = ql; }
    else {
        j -= nq4; isq = 0;
        if (j >= nk4) { j -= nk4; isv = 1; dh = vh; dl = vl; coloff = NQ + NKVD; }
        else          {                    dh = kh; dl = kl; coloff = NQ; }
    }
    int g = j % HD4;                              // float4 group in head
    int h = (j / HD4) % nh;
    int s = (j / (HD4 * nh)) % SEQ;
    int b = j / (HD4 * nh * SEQ);

    float4 x = *(const float4*)(qkv + (size_t)(b * SEQ + s) * NQKV + coloff + h * HD + 4 * g);
    float o0, o1, o2, o3;
    if (isv) { o0 = x.x; o1 = x.y; o2 = x.z; o3 = x.w; }
    else {
        float2 cs0 = *(const float2*)(cos_ + s * (HD / 2) + 2 * g);
        float2 sn0 = *(const float2*)(sin_ + s * (HD / 2) + 2 * g);
        float sc = isq ? qscale : 1.0f;
        o0 = (x.x * cs0.x - x.y * sn0.x) * sc;
        o1 = (x.x * sn0.x + x.y * cs0.x) * sc;
        o2 = (x.z * cs0.y - x.w * sn0.y) * sc;
        o3 = (x.z * sn0.y + x.w * cs0.y) * sc;
    }
    uint32_t h01 = packbf(o0, o1), h23 = packbf(o2, o3);
    __nv_bfloat162 b01 = *(__nv_bfloat162*)&h01;
    __nv_bfloat162 b23 = *(__nv_bfloat162*)&h23;
    uint32_t l01 = packbf(o0 - __bfloat162float(b01.x), o1 - __bfloat162float(b01.y));
    uint32_t l23 = packbf(o2 - __bfloat162float(b23.x), o3 - __bfloat162float(b23.y));
    size_t o = ((size_t)(b * nh + h) * SEQ + s) * HD + 4 * g;
    *(uint2*)(dh + o) = make_uint2(h01, h23);
    *(uint2*)(dl + o) = make_uint2(l01, l23);
}

// ============================================================
// flash attention v4 (R11 winner, byte-identical): 512 threads,
// 128 q-rows/CTA, no online max, register-resident P (3-term PV).
// ============================================================
#define NTILE (SEQ/64)
#define AKV_STG 65536u
#define AQ_OFF  131072u
#define ARED_OFF 196608u
#define ATT_SMEM 198656

__global__ void __launch_bounds__(512, 1) attn_mma(
    const __nv_bfloat16* __restrict__ qh, const __nv_bfloat16* __restrict__ ql,
    const __nv_bfloat16* __restrict__ kh, const __nv_bfloat16* __restrict__ kl,
    const __nv_bfloat16* __restrict__ vh, const __nv_bfloat16* __restrict__ vl,
    __nv_bfloat16* __restrict__ outh, __nv_bfloat16* __restrict__ outl)
{
    extern __shared__ char sm[];
    const uint32_t sb = smem_u32(sm);
    const int t = threadIdx.x, lane = t & 31, w = t >> 5;
    const int wm = w & 7, wn = w >> 3;
    const int qt = blockIdx.x, h = blockIdx.y, b = blockIdx.z;
    const int kvh = h >> 2;

    const __nv_bfloat16* qhg = qh + ((size_t)(b * NH + h) * SEQ + qt * 128) * HD;
    const __nv_bfloat16* qlg = ql + ((size_t)(b * NH + h) * SEQ + qt * 128) * HD;
    const size_t kvb = (size_t)(b * NKV + kvh) * SEQ * HD;

    {
        int r = t >> 2, seg = t & 3;
        #pragma unroll
        for (int j = 0; j < 4; j++) {
            int boff = seg * 64 + j * 16;
            uint4 a = *(const uint4*)(qhg + (size_t)r * HD + boff / 2);
            *(uint4*)(sm + AQ_OFF + sw256(r, boff)) = a;
            uint4 c = *(const uint4*)(qlg + (size_t)r * HD + boff / 2);
            *(uint4*)(sm + AQ_OFF + 32768u + sw256(r, boff)) = c;
        }
    }

    const int lrow = t >> 3, lsg = t & 7;
#define LOAD_KV(kt, stg) do {                                                   \
    uint32_t bufb = sb + (uint32_t)(stg) * AKV_STG;                             \
    size_t grow = kvb + ((size_t)(kt) * 64 + lrow) * HD;                        \
    _Pragma("unroll")                                                           \
    for (int j = 0; j < 2; j++) {                                               \
        int boff = lsg * 32 + j * 16;                                           \
        uint32_t sd = sw256(lrow, boff);                                        \
        cp16(bufb + sd,          kh + grow + boff / 2);                         \
        cp16(bufb + 16384u + sd, kl + grow + boff / 2);                         \
        cp16(bufb + 32768u + sd, vh + grow + boff / 2);                         \
        cp16(bufb + 49152u + sd, vl + grow + boff / 2);                         \
    }                                                                           \
} while (0)

    LOAD_KV(0, 0); CP_COMMIT();

    float lp[2] = {0.f, 0.f};
    float oacc[16][4];
    #pragma unroll
    for (int i = 0; i < 16; i++)
        #pragma unroll
        for (int j = 0; j < 4; j++) oacc[i][j] = 0.f;

    const int row1 = wm * 16 + (lane >> 2);
    const int row2 = row1 + 8;
    const int qar = wm * 16 + (lane & 7) + ((lane >> 3) & 1) * 8;
    const int qab = (lane >> 4) * 16;

    for (int kt = 0; kt < NTILE; kt++) {
        if (kt + 1 < NTILE) { LOAD_KV(kt + 1, (kt + 1) & 1); CP_COMMIT(); CP_WAIT1(); }
        else                { CP_WAIT0(); }
        __syncthreads();
        const uint32_t kbuf = sb + (uint32_t)(kt & 1) * AKV_STG;
        const uint32_t vbuf = kbuf + 32768u;

        float sacc[4][4];
        #pragma unroll
        for (int i = 0; i < 4; i++)
            #pragma unroll
            for (int j = 0; j < 4; j++) sacc[i][j] = 0.f;
        {
            int br = wn * 32 + (lane & 7) + (lane >> 4) * 8;
            int bb0 = ((lane >> 3) & 1) * 16;
            #pragma unroll
            for (int ks = 0; ks < 8; ks++) {
                uint32_t qfh[4], qfl[4];
                uint32_t qoff = sw256(qar, ks * 32 + qab);
                ldsm4(qfh, sb + AQ_OFF + qoff);
                ldsm4(qfl, sb + AQ_OFF + 32768u + qoff);
                #pragma unroll
                for (int np = 0; np < 2; np++) {
                    uint32_t bh[4], bl[4];
                    uint32_t off = sw256(br + np * 16, ks * 32 + bb0);
                    ldsm4(bh, kbuf + off);
                    ldsm4(bl, kbuf + 16384u + off);
                    mma16816(sacc[np * 2],     qfh, bh + 0);
                    mma16816(sacc[np * 2],     qfh, bl + 0);
                    mma16816(sacc[np * 2],     qfl, bh + 0);
                    mma16816(sacc[np * 2 + 1], qfh, bh + 2);
                    mma16816(sacc[np * 2 + 1], qfh, bl + 2);
                    mma16816(sacc[np * 2 + 1], qfl, bh + 2);
                }
            }
        }

        float p[4][4];
        #pragma unroll
        for (int nt = 0; nt < 4; nt++) {
            p[nt][0] = __expf(sacc[nt][0]);
            p[nt][1] = __expf(sacc[nt][1]);
            p[nt][2] = __expf(sacc[nt][2]);
            p[nt][3] = __expf(sacc[nt][3]);
            lp[0] += p[nt][0] + p[nt][1];
            lp[1] += p[nt][2] + p[nt][3];
        }

        {
            int vr0 = (lane & 7) + ((lane >> 3) & 1) * 8;
            int vc0 = (lane >> 4) * 16;
            #pragma unroll
            for (int kb = 0; kb < 2; kb++) {
                uint32_t pfh[4], pfl[4];
                {
                    const float* t0 = p[kb * 2];
                    const float* t1 = p[kb * 2 + 1];
                    pfh[0] = packbf(t0[0], t0[1]);
                    pfh[1] = packbf(t0[2], t0[3]);
                    pfh[2] = packbf(t1[0], t1[1]);
                    pfh[3] = packbf(t1[2], t1[3]);
                    __nv_bfloat162 h0 = *(__nv_bfloat162*)&pfh[0];
                    __nv_bfloat162 h1 = *(__nv_bfloat162*)&pfh[1];
                    __nv_bfloat162 h2 = *(__nv_bfloat162*)&pfh[2];
                    __nv_bfloat162 h3 = *(__nv_bfloat162*)&pfh[3];
                    pfl[0] = packbf(t0[0] - __bfloat162float(h0.x), t0[1] - __bfloat162float(h0.y));
                    pfl[1] = packbf(t0[2] - __bfloat162float(h1.x), t0[3] - __bfloat162float(h1.y));
                    pfl[2] = packbf(t1[0] - __bfloat162float(h2.x), t1[1] - __bfloat162float(h2.y));
                    pfl[3] = packbf(t1[2] - __bfloat162float(h3.x), t1[3] - __bfloat162float(h3.y));
                }
                int vrow = wn * 32 + kb * 16 + vr0;
                #pragma unroll
                for (int db = 0; db < 8; db++) {
                    uint32_t wh[4], wl[4];
                    uint32_t off = sw256(vrow, db * 32 + vc0);
                    ldsm4t(wh, vbuf + off);
                    ldsm4t(wl, vbuf + 16384u + off);
                    mma16816(oacc[db * 2],     pfh, wh + 0);
                    mma16816(oacc[db * 2],     pfh, wl + 0);
                    mma16816(oacc[db * 2],     pfl, wh + 0);
                    mma16816(oacc[db * 2 + 1], pfh, wh + 2);
                    mma16816(oacc[db * 2 + 1], pfh, wl + 2);
                    mma16816(oacc[db * 2 + 1], pfl, wh + 2);
                }
            }
        }
        __syncthreads();
    }

    {
        lp[0] += __shfl_xor_sync(0xffffffffu, lp[0], 1);
        lp[0] += __shfl_xor_sync(0xffffffffu, lp[0], 2);
        lp[1] += __shfl_xor_sync(0xffffffffu, lp[1], 1);
        lp[1] += __shfl_xor_sync(0xffffffffu, lp[1], 2);
        float* reds = (float*)(sm + ARED_OFF);
        if ((lane & 3) == 0) {
            reds[wn * 128 + row1] = lp[0];
            reds[wn * 128 + row2] = lp[1];
        }
        float* ox = (float*)sm;
        if (wn == 1) {
            #pragma unroll
            for (int nt = 0; nt < 16; nt++) {
                int c0 = nt * 8 + (lane & 3) * 2;
                *(float2*)(ox + (size_t)row1 * 128 + c0) = make_float2(oacc[nt][0], oacc[nt][1]);
                *(float2*)(ox + (size_t)row2 * 128 + c0) = make_float2(oacc[nt][2], oacc[nt][3]);
            }
        }
        __syncthreads();
        if (wn == 0) {
            float inv1 = 1.f / (reds[row1] + reds[128 + row1]);
            float inv2 = 1.f / (reds[row2] + reds[128 + row2]);
            int rg1 = qt * 128 + row1, rg2 = qt * 128 + row2;
            size_t b1 = ((size_t)(b * SEQ + rg1) * NH + h) * HD;
            size_t b2 = ((size_t)(b * SEQ + rg2) * NH + h) * HD;
            #pragma unroll
            for (int nt = 0; nt < 16; nt++) {
                int c0 = nt * 8 + (lane & 3) * 2;
                float2 x1 = *(float2*)(ox + (size_t)row1 * 128 + c0);
                float2 x2 = *(float2*)(ox + (size_t)row2 * 128 + c0);
                float f0 = (oacc[nt][0] + x1.x) * inv1;
                float f1 = (oacc[nt][1] + x1.y) * inv1;
                float f2 = (oacc[nt][2] + x2.x) * inv2;
                float f3 = (oacc[nt][3] + x2.y) * inv2;
                uint32_t h01 = packbf(f0, f1), h23 = packbf(f2, f3);
                __nv_bfloat162 bb01 = *(__nv_bfloat162*)&h01;
                __nv_bfloat162 bb23 = *(__nv_bfloat162*)&h23;
                uint32_t l01 = packbf(f0 - __bfloat162float(bb01.x), f1 - __bfloat162float(bb01.y));
                uint32_t l23 = packbf(f2 - __bfloat162float(bb23.x), f3 - __bfloat162float(bb23.y));
                *(uint32_t*)(outh + b1 + c0) = h01;
                *(uint32_t*)(outh + b2 + c0) = h23;
                *(uint32_t*)(outl + b1 + c0) = l01;
                *(uint32_t*)(outl + b2 + c0) = l23;
            }
        }
    }
#undef LOAD_KV
}

// ============================================================
// launch  (R11 structure)
// ============================================================
extern "C" void kernel_launch(void* const* d_in, const int* in_sizes, int n_in,
                              void* d_out, int out_size)
{
    const float* x  = (const float*)d_in[0];
    const float* wq = (const float*)d_in[1];
    const float* wk = (const float*)d_in[2];
    const float* wv = (const float*)d_in[3];
    const float* wo = (const float*)d_in[4];
    const float* fcos = (const float*)d_in[7];
    const float* fsin = (const float*)d_in[8];
    float* out = (float*)d_out;

    float* gqkv;
    __nv_bfloat16 *xh, *xl, *wqkvTh, *wqkvTl, *woTh, *woTl;
    __nv_bfloat16 *aoh, *aol, *pqh, *pql, *pkh, *pkl, *pvh, *pvl;
    cudaGetSymbolAddress((void**)&gqkv, g_qkv);
    cudaGetSymbolAddress((void**)&xh, g_xh);         cudaGetSymbolAddress((void**)&xl, g_xl);
    cudaGetSymbolAddress((void**)&wqkvTh, g_wqkvTh); cudaGetSymbolAddress((void**)&wqkvTl, g_wqkvTl);
    cudaGetSymbolAddress((void**)&woTh, g_woTh);     cudaGetSymbolAddress((void**)&woTl, g_woTl);
    cudaGetSymbolAddress((void**)&aoh, g_aoh);       cudaGetSymbolAddress((void**)&aol, g_aol);
    cudaGetSymbolAddress((void**)&pqh, g_qh);        cudaGetSymbolAddress((void**)&pql, g_ql);
    cudaGetSymbolAddress((void**)&pkh, g_kh);        cudaGetSymbolAddress((void**)&pkl, g_kl);
    cudaGetSymbolAddress((void**)&pvh, g_vh);        cudaGetSymbolAddress((void**)&pvl, g_vl);

    cudaFuncSetAttribute(gemm_mma, cudaFuncAttributeMaxDynamicSharedMemorySize, GEMM_SMEM);
    cudaFuncSetAttribute(attn_mma, cudaFuncAttributeMaxDynamicSharedMemorySize, ATT_SMEM);

    // 0: prep
    prep_kernel<<<PREP_TOTAL, 256>>>(x, wq, wk, wv, wo, xh, xl, wqkvTh, wqkvTl, woTh, woTl);
    // 1: fused qkv projection
    gemm_mma<<<dim3(NQKV / BN, MTOT / BM), 512, GEMM_SMEM>>>(xh, xl, wqkvTh, wqkvTl,
                                                             gqkv, MTOT, NQKV, DIM);
    // 2: rope + split + relayout (float4 per thread)
    {
        int total = BATCH * SEQ * (NH + 2 * NKV) * (HD / 4);
        rope_split<<<(total + 255) / 256, 256>>>(gqkv, fcos, fsin,
                                                 pqh, pql, pkh, pkl, pvh, pvl);
    }
    // 3: attention  <-- ncu capture slot
    {
        dim3 grid(SEQ / 128, NH, BATCH);
        attn_mma<<<grid, 512, ATT_SMEM>>>(pqh, pql, pkh, pkl, pvh, pvl, aoh, aol);
    }
    // 4: output projection
    gemm_mma<<<dim3(DIM / BN, MTOT / BM), 512, GEMM_SMEM>>>(aoh, aol, woTh, woTl, out, MTOT, DIM, NQ);
}

// round 17
// speedup vs baseline: 1.0770x; 1.0123x over previous
#include <cuda_runtime.h>
#include <cuda_bf16.h>
#include <cstdint>
#include <math.h>

#define BATCH 2
#define SEQ   2048
#define DIM   4096
#define NH    32
#define NKV   8
#define HD    128
#define NREP  4
#define MTOT  (BATCH*SEQ)   // 4096
#define NQ    (NH*HD)       // 4096
#define NKVD  (NKV*HD)      // 1024
#define NQKV  (NQ + 2*NKVD) // 6144

// -------- scratch (device globals) --------
__device__ float g_qkv[(size_t)MTOT*NQKV];

__device__ __nv_bfloat16 g_xh[(size_t)MTOT*DIM],   g_xl[(size_t)MTOT*DIM];
__device__ __nv_bfloat16 g_wqkvTh[(size_t)NQKV*DIM], g_wqkvTl[(size_t)NQKV*DIM];
__device__ __nv_bfloat16 g_woTh[(size_t)DIM*NQ],   g_woTl[(size_t)DIM*NQ];
__device__ __nv_bfloat16 g_aoh[(size_t)MTOT*NQ],   g_aol[(size_t)MTOT*NQ];
__device__ __nv_bfloat16 g_qh[(size_t)MTOT*NQ],    g_ql[(size_t)MTOT*NQ];
__device__ __nv_bfloat16 g_kh[(size_t)MTOT*NKVD],  g_kl[(size_t)MTOT*NKVD];
__device__ __nv_bfloat16 g_vh[(size_t)MTOT*NKVD],  g_vl[(size_t)MTOT*NKVD];

// ============================================================
// PTX helpers
// ============================================================
__device__ __forceinline__ uint32_t smem_u32(const void* p) {
    uint32_t a;
    asm("{ .reg .u64 t; cvta.to.shared.u64 t, %1; cvt.u32.u64 %0, t; }" : "=r"(a) : "l"(p));
    return a;
}
__device__ __forceinline__ void cp16(uint32_t dst, const void* src) {
    asm volatile("cp.async.cg.shared.global [%0], [%1], 16;" :: "r"(dst), "l"(src));
}
#define CP_COMMIT()  asm volatile("cp.async.commit_group;")
#define CP_WAIT1()   asm volatile("cp.async.wait_group 1;")
#define CP_WAIT0()   asm volatile("cp.async.wait_group 0;")

__device__ __forceinline__ void ldsm4(uint32_t* r, uint32_t addr) {
    asm volatile("ldmatrix.sync.aligned.m8n8.x4.shared.b16 {%0,%1,%2,%3}, [%4];"
        : "=r"(r[0]), "=r"(r[1]), "=r"(r[2]), "=r"(r[3]) : "r"(addr));
}
__device__ __forceinline__ void ldsm4t(uint32_t* r, uint32_t addr) {
    asm volatile("ldmatrix.sync.aligned.m8n8.x4.trans.shared.b16 {%0,%1,%2,%3}, [%4];"
        : "=r"(r[0]), "=r"(r[1]), "=r"(r[2]), "=r"(r[3]) : "r"(addr));
}
__device__ __forceinline__ void mma16816(float* c, const uint32_t* a, const uint32_t* b) {
    asm volatile("mma.sync.aligned.m16n8k16.row.col.f32.bf16.bf16.f32 "
        "{%0,%1,%2,%3}, {%4,%5,%6,%7}, {%8,%9}, {%0,%1,%2,%3};"
        : "+f"(c[0]), "+f"(c[1]), "+f"(c[2]), "+f"(c[3])
        : "r"(a[0]), "r"(a[1]), "r"(a[2]), "r"(a[3]), "r"(b[0]), "r"(b[1]));
}
__device__ __forceinline__ uint32_t packbf(float a, float b) {
    __nv_bfloat162 v = __floats2bfloat162_rn(a, b);
    return *(uint32_t*)&v;
}

__device__ __forceinline__ uint32_t swz(int row, int seg) {     // 64B rows, 4 segs
    return (uint32_t)row * 64u + ((uint32_t)(seg ^ ((row >> 1) & 3)) << 4);
}
__device__ __forceinline__ uint32_t sw256(int row, int boff) {
    return (uint32_t)row * 256u + (uint32_t)(boff ^ ((row & 7) << 4));
}

// ============================================================
// split-bf16 GEMM (proven 2-stage BK=32): CTA 128x128, 512 threads
// (16 warps 4x4), warp tile 32x32.  Byte-identical to R16.
// ============================================================
#define BM 128
#define BN 128
#define BK 32
#define GOFF_AH 0u
#define GOFF_AL 8192u
#define GOFF_BH 16384u
#define GOFF_BL 24576u
#define GSTAGE  32768u
#define GEMM_SMEM (2*32768)

__global__ void __launch_bounds__(512, 1) gemm_mma(
    const __nv_bfloat16* __restrict__ Ah, const __nv_bfloat16* __restrict__ Al,
    const __nv_bfloat16* __restrict__ Bh, const __nv_bfloat16* __restrict__ Bl,
    float* __restrict__ C, int M, int N, int K)
{
    extern __shared__ char smem[];
    const uint32_t sb = smem_u32(smem);
    const int t = threadIdx.x;
    const int lane = t & 31, wid = t >> 5;
    const int m0 = blockIdx.y * BM, n0 = blockIdx.x * BN;

    const int lrow = t >> 2, lseg = t & 3;
    const __nv_bfloat16* gAh = Ah + (size_t)(m0 + lrow) * K + lseg * 8;
    const __nv_bfloat16* gAl = Al + (size_t)(m0 + lrow) * K + lseg * 8;
    const __nv_bfloat16* gBh = Bh + (size_t)(n0 + lrow) * K + lseg * 8;
    const __nv_bfloat16* gBl = Bl + (size_t)(n0 + lrow) * K + lseg * 8;
    const uint32_t loff = swz(lrow, lseg);

#define LOAD_CHUNK(k0, base) do {                   \
    cp16((base) + GOFF_AH + loff, gAh + (k0));      \
    cp16((base) + GOFF_AL + loff, gAl + (k0));      \
    cp16((base) + GOFF_BH + loff, gBh + (k0));      \
    cp16((base) + GOFF_BL + loff, gBl + (k0));      \
} while (0)

    const int wm = (wid & 3) * 32;
    const int wn = (wid >> 2) * 32;
    const int arow = wm + (lane & 7) + ((lane >> 3) & 1) * 8;
    const int aseg = lane >> 4;
    const int brow = wn + (lane & 7) + ((lane >> 4) & 1) * 8;
    const int bseg = (lane >> 3) & 1;

    float acc[2][4][4];
    #pragma unroll
    for (int i = 0; i < 2; i++)
        #pragma unroll
        for (int j = 0; j < 4; j++)
            #pragma unroll
            for (int v = 0; v < 4; v++) acc[i][j][v] = 0.f;

    const int nch = K / BK;
    LOAD_CHUNK(0, sb);            CP_COMMIT();
    LOAD_CHUNK(BK, sb + GSTAGE);  CP_COMMIT();

    for (int ch = 0; ch < nch; ch++) {
        CP_WAIT1();
        __syncthreads();
        const uint32_t base = sb + (uint32_t)(ch & 1) * GSTAGE;

        #pragma unroll
        for (int ks = 0; ks < 2; ks++) {
            uint32_t ah[2][4], al[2][4], bh[2][4], bl[2][4];
            #pragma unroll
            for (int mt = 0; mt < 2; mt++) {
                uint32_t off = swz(arow + mt * 16, ks * 2 + aseg);
                ldsm4(ah[mt], base + GOFF_AH + off);
                ldsm4(al[mt], base + GOFF_AL + off);
            }
            #pragma unroll
            for (int np = 0; np < 2; np++) {
                uint32_t off = swz(brow + np * 16, ks * 2 + bseg);
                ldsm4(bh[np], base + GOFF_BH + off);
                ldsm4(bl[np], base + GOFF_BL + off);
            }
            #pragma unroll
            for (int np = 0; np < 2; np++)
                #pragma unroll
                for (int mt = 0; mt < 2; mt++) {
                    mma16816(acc[mt][np * 2],     ah[mt], bh[np] + 0);
                    mma16816(acc[mt][np * 2],     ah[mt], bl[np] + 0);
                    mma16816(acc[mt][np * 2],     al[mt], bh[np] + 0);
                    mma16816(acc[mt][np * 2 + 1], ah[mt], bh[np] + 2);
                    mma16816(acc[mt][np * 2 + 1], ah[mt], bl[np] + 2);
                    mma16816(acc[mt][np * 2 + 1], al[mt], bh[np] + 2);
                }
        }
        __syncthreads();
        if (ch + 2 < nch) LOAD_CHUNK((ch + 2) * BK, base);
        CP_COMMIT();
    }

    #pragma unroll
    for (int mt = 0; mt < 2; mt++) {
        int r0 = m0 + wm + mt * 16 + (lane >> 2);
        #pragma unroll
        for (int nt = 0; nt < 4; nt++) {
            int c0 = n0 + wn + nt * 8 + (lane & 3) * 2;
            *(float2*)(C + (size_t)r0 * N + c0)       = make_float2(acc[mt][nt][0], acc[mt][nt][1]);
            *(float2*)(C + (size_t)(r0 + 8) * N + c0) = make_float2(acc[mt][nt][2], acc[mt][nt][3]);
        }
    }
#undef LOAD_CHUNK
}

// ============================================================
// prep: fused x-split + qkv weight transpose + wo transpose (one launch)
// ============================================================
#define PREP_SPLIT_BLKS 32768
#define PREP_QKV_BLKS   24576
#define PREP_TOTAL      (PREP_SPLIT_BLKS + PREP_QKV_BLKS + 16384)

__global__ void __launch_bounds__(256) prep_kernel(
    const float* __restrict__ x,  const float* __restrict__ Wq,
    const float* __restrict__ Wk, const float* __restrict__ Wv,
    const float* __restrict__ Wo,
    __nv_bfloat16* __restrict__ xh,  __nv_bfloat16* __restrict__ xl,
    __nv_bfloat16* __restrict__ qkvTh, __nv_bfloat16* __restrict__ qkvTl,
    __nv_bfloat16* __restrict__ woTh,  __nv_bfloat16* __restrict__ woTl)
{
    __shared__ float tile[32][33];
    int bid = blockIdx.x, t = threadIdx.x;

    if (bid < PREP_SPLIT_BLKS) {
        int i = bid * 256 + t;
        float2 v = ((const float2*)x)[i];
        __nv_bfloat16 hx = __float2bfloat16(v.x), hy = __float2bfloat16(v.y);
        ((__nv_bfloat162*)xh)[i] = __halves2bfloat162(hx, hy);
        ((__nv_bfloat162*)xl)[i] = __halves2bfloat162(
            __float2bfloat16(v.x - __bfloat162float(hx)),
            __float2bfloat16(v.y - __bfloat162float(hy)));
        return;
    }

    int tx = t & 31, ty = t >> 5;
    const float* src; __nv_bfloat16 *Th, *Tl;
    int srcN, outK, nsrc, rowoff, by;
    if (bid < PREP_SPLIT_BLKS + PREP_QKV_BLKS) {
        int b2 = bid - PREP_SPLIT_BLKS;
        int bx = b2 % 192; by = b2 / 192;
        Th = qkvTh; Tl = qkvTl; outK = DIM;
        if (bx < 128)      { src = Wq; srcN = NQ;   nsrc = bx * 32;         rowoff = 0;    }
        else if (bx < 160) { src = Wk; srcN = NKVD; nsrc = (bx - 128) * 32; rowoff = NQ;   }
        else               { src = Wv; srcN = NKVD; nsrc = (bx - 160) * 32; rowoff = NQ + NKVD; }
    } else {
        int b2 = bid - PREP_SPLIT_BLKS - PREP_QKV_BLKS;
        int bx = b2 % 128; by = b2 / 128;
        Th = woTh; Tl = woTl; outK = NQ;
        src = Wo; srcN = DIM; nsrc = bx * 32; rowoff = 0;
    }

    int n = nsrc + tx;
    #pragma unroll
    for (int j = 0; j < 4; j++) {
        int k = by * 32 + ty + j * 8;
        tile[ty + j * 8][tx] = src[(size_t)k * srcN + n];
    }
    __syncthreads();
    int k2 = by * 32 + tx;
    #pragma unroll
    for (int j = 0; j < 4; j++) {
        int n2 = rowoff + nsrc + ty + j * 8;
        float v = tile[tx][ty + j * 8];
        __nv_bfloat16 h = __float2bfloat16(v);
        Th[(size_t)n2 * outK + k2] = h;
        Tl[(size_t)n2 * outK + k2] = __float2bfloat16(v - __bfloat162float(h));
    }
}

// ============================================================
// rope + layout change + hi/lo split — float4 (2 complex pairs)/thread
// ============================================================
__global__ void rope_split(const float* __restrict__ qkv,
                           const float* __restrict__ cos_, const float* __restrict__ sin_,
                           __nv_bfloat16* qh, __nv_bfloat16* ql,
                           __nv_bfloat16* kh, __nv_bfloat16* kl,
                           __nv_bfloat16* vh, __nv_bfloat16* vl)
{
    const int HD4 = HD / 4;
    const int nq4 = BATCH * SEQ * NH * HD4;
    const int nk4 = BATCH * SEQ * NKV * HD4;
    const float qscale = 0.08838834764831845f;
    int idx = blockIdx.x * blockDim.x + threadIdx.x;
    if (idx >= nq4 + 2 * nk4) return;

    int j = idx, isq = 1, isv = 0;
    const int nh = (idx < nq4) ? NH : NKV;
    int coloff = 0;
    __nv_bfloat16 *dh, *dl;
    if (idx < nq4) { dh = qh; dl = ql; }
    else {
        j -= nq4; isq = 0;
        if (j >= nk4) { j -= nk4; isv = 1; dh = vh; dl = vl; coloff = NQ + NKVD; }
        else          {                    dh = kh; dl = kl; coloff = NQ; }
    }
    int g = j % HD4;
    int h = (j / HD4) % nh;
    int s = (j / (HD4 * nh)) % SEQ;
    int b = j / (HD4 * nh * SEQ);

    float4 x = *(const float4*)(qkv + (size_t)(b * SEQ + s) * NQKV + coloff + h * HD + 4 * g);
    float o0, o1, o2, o3;
    if (isv) { o0 = x.x; o1 = x.y; o2 = x.z; o3 = x.w; }
    else {
        float2 cs0 = *(const float2*)(cos_ + s * (HD / 2) + 2 * g);
        float2 sn0 = *(const float2*)(sin_ + s * (HD / 2) + 2 * g);
        float sc = isq ? qscale : 1.0f;
        o0 = (x.x * cs0.x - x.y * sn0.x) * sc;
        o1 = (x.x * sn0.x + x.y * cs0.x) * sc;
        o2 = (x.z * cs0.y - x.w * sn0.y) * sc;
        o3 = (x.z * sn0.y + x.w * cs0.y) * sc;
    }
    uint32_t h01 = packbf(o0, o1), h23 = packbf(o2, o3);
    __nv_bfloat162 b01 = *(__nv_bfloat162*)&h01;
    __nv_bfloat162 b23 = *(__nv_bfloat162*)&h23;
    uint32_t l01 = packbf(o0 - __bfloat162float(b01.x), o1 - __bfloat162float(b01.y));
    uint32_t l23 = packbf(o2 - __bfloat162float(b23.x), o3 - __bfloat162float(b23.y));
    size_t o = ((size_t)(b * nh + h) * SEQ + s) * HD + 4 * g;
    *(uint2*)(dh + o) = make_uint2(h01, h23);
    *(uint2*)(dl + o) = make_uint2(l01, l23);
}

// ============================================================
// flash attention v6: single barrier per tile. Prefetch of kt+1 is
// issued AFTER the top barrier, which (by program order) proves all
// warps finished kt-1's PV reads of the stage being overwritten.
// Stage-kt readiness: per-thread CP_WAIT0 before the barrier.
// ============================================================
#define NTILE (SEQ/64)
#define AKV_STG 65536u
#define AQ_OFF  131072u
#define ARED_OFF 196608u
#define ATT_SMEM 198656

__global__ void __launch_bounds__(512, 1) attn_mma(
    const __nv_bfloat16* __restrict__ qh, const __nv_bfloat16* __restrict__ ql,
    const __nv_bfloat16* __restrict__ kh, const __nv_bfloat16* __restrict__ kl,
    const __nv_bfloat16* __restrict__ vh, const __nv_bfloat16* __restrict__ vl,
    __nv_bfloat16* __restrict__ outh, __nv_bfloat16* __restrict__ outl)
{
    extern __shared__ char sm[];
    const uint32_t sb = smem_u32(sm);
    const int t = threadIdx.x, lane = t & 31, w = t >> 5;
    const int wm = w & 7, wn = w >> 3;
    const int qt = blockIdx.x, h = blockIdx.y, b = blockIdx.z;
    const int kvh = h >> 2;

    const __nv_bfloat16* qhg = qh + ((size_t)(b * NH + h) * SEQ + qt * 128) * HD;
    const __nv_bfloat16* qlg = ql + ((size_t)(b * NH + h) * SEQ + qt * 128) * HD;
    const size_t kvb = (size_t)(b * NKV + kvh) * SEQ * HD;

    {
        int r = t >> 2, seg = t & 3;
        #pragma unroll
        for (int j = 0; j < 4; j++) {
            int boff = seg * 64 + j * 16;
            uint4 a = *(const uint4*)(qhg + (size_t)r * HD + boff / 2);
            *(uint4*)(sm + AQ_OFF + sw256(r, boff)) = a;
            uint4 c = *(const uint4*)(qlg + (size_t)r * HD + boff / 2);
            *(uint4*)(sm + AQ_OFF + 32768u + sw256(r, boff)) = c;
        }
    }

    const int lrow = t >> 3, lsg = t & 7;
#define LOAD_KV(kt, stg) do {                                                   \
    uint32_t bufb = sb + (uint32_t)(stg) * AKV_STG;                             \
    size_t grow = kvb + ((size_t)(kt) * 64 + lrow) * HD;                        \
    _Pragma("unroll")                                                           \
    for (int j = 0; j < 2; j++) {                                               \
        int boff = lsg * 32 + j * 16;                                           \
        uint32_t sd = sw256(lrow, boff);                                        \
        cp16(bufb + sd,          kh + grow + boff / 2);                         \
        cp16(bufb + 16384u + sd, kl + grow + boff / 2);                         \
        cp16(bufb + 32768u + sd, vh + grow + boff / 2);                         \
        cp16(bufb + 49152u + sd, vl + grow + boff / 2);                         \
    }                                                                           \
} while (0)

    LOAD_KV(0, 0); CP_COMMIT();

    float lp[2] = {0.f, 0.f};
    float oacc[16][4];
    #pragma unroll
    for (int i = 0; i < 16; i++)
        #pragma unroll
        for (int j = 0; j < 4; j++) oacc[i][j] = 0.f;

    const int row1 = wm * 16 + (lane >> 2);
    const int row2 = row1 + 8;
    const int qar = wm * 16 + (lane & 7) + ((lane >> 3) & 1) * 8;
    const int qab = (lane >> 4) * 16;

    for (int kt = 0; kt < NTILE; kt++) {
        CP_WAIT0();                 // stage kt data (this thread's copies) landed
        __syncthreads();            // publish; also proves all warps done with kt-1 PV
        if (kt + 1 < NTILE) { LOAD_KV(kt + 1, (kt + 1) & 1); CP_COMMIT(); }
        const uint32_t kbuf = sb + (uint32_t)(kt & 1) * AKV_STG;
        const uint32_t vbuf = kbuf + 32768u;

        float sacc[4][4];
        #pragma unroll
        for (int i = 0; i < 4; i++)
            #pragma unroll
            for (int j = 0; j < 4; j++) sacc[i][j] = 0.f;
        {
            int br = wn * 32 + (lane & 7) + (lane >> 4) * 8;
            int bb0 = ((lane >> 3) & 1) * 16;
            #pragma unroll
            for (int ks = 0; ks < 8; ks++) {
                uint32_t qfh[4], qfl[4];
                uint32_t qoff = sw256(qar, ks * 32 + qab);
                ldsm4(qfh, sb + AQ_OFF + qoff);
                ldsm4(qfl, sb + AQ_OFF + 32768u + qoff);
                #pragma unroll
                for (int np = 0; np < 2; np++) {
                    uint32_t bh[4], bl[4];
                    uint32_t off = sw256(br + np * 16, ks * 32 + bb0);
                    ldsm4(bh, kbuf + off);
                    ldsm4(bl, kbuf + 16384u + off);
                    mma16816(sacc[np * 2],     qfh, bh + 0);
                    mma16816(sacc[np * 2],     qfh, bl + 0);
                    mma16816(sacc[np * 2],     qfl, bh + 0);
                    mma16816(sacc[np * 2 + 1], qfh, bh + 2);
                    mma16816(sacc[np * 2 + 1], qfh, bl + 2);
                    mma16816(sacc[np * 2 + 1], qfl, bh + 2);
                }
            }
        }

        float p[4][4];
        #pragma unroll
        for (int nt = 0; nt < 4; nt++) {
            p[nt][0] = __expf(sacc[nt][0]);
            p[nt][1] = __expf(sacc[nt][1]);
            p[nt][2] = __expf(sacc[nt][2]);
            p[nt][3] = __expf(sacc[nt][3]);
            lp[0] += p[nt][0] + p[nt][1];
            lp[1] += p[nt][2] + p[nt][3];
        }

        {
            int vr0 = (lane & 7) + ((lane >> 3) & 1) * 8;
            int vc0 = (lane >> 4) * 16;
            #pragma unroll
            for (int kb = 0; kb < 2; kb++) {
                uint32_t pfh[4], pfl[4];
                {
                    const float* t0 = p[kb * 2];
                    const float* t1 = p[kb * 2 + 1];
                    pfh[0] = packbf(t0[0], t0[1]);
                    pfh[1] = packbf(t0[2], t0[3]);
                    pfh[2] = packbf(t1[0], t1[1]);
                    pfh[3] = packbf(t1[2], t1[3]);
                    __nv_bfloat162 h0 = *(__nv_bfloat162*)&pfh[0];
                    __nv_bfloat162 h1 = *(__nv_bfloat162*)&pfh[1];
                    __nv_bfloat162 h2 = *(__nv_bfloat162*)&pfh[2];
                    __nv_bfloat162 h3 = *(__nv_bfloat162*)&pfh[3];
                    pfl[0] = packbf(t0[0] - __bfloat162float(h0.x), t0[1] - __bfloat162float(h0.y));
                    pfl[1] = packbf(t0[2] - __bfloat162float(h1.x), t0[3] - __bfloat162float(h1.y));
                    pfl[2] = packbf(t1[0] - __bfloat162float(h2.x), t1[1] - __bfloat162float(h2.y));
                    pfl[3] = packbf(t1[2] - __bfloat162float(h3.x), t1[3] - __bfloat162float(h3.y));
                }
                int vrow = wn * 32 + kb * 16 + vr0;
                #pragma unroll
                for (int db = 0; db < 8; db++) {
                    uint32_t wh[4], wl[4];
                    uint32_t off = sw256(vrow, db * 32 + vc0);
                    ldsm4t(wh, vbuf + off);
                    ldsm4t(wl, vbuf + 16384u + off);
                    mma16816(oacc[db * 2],     pfh, wh + 0);
                    mma16816(oacc[db * 2],     pfh, wl + 0);
                    mma16816(oacc[db * 2],     pfl, wh + 0);
                    mma16816(oacc[db * 2 + 1], pfh, wh + 2);
                    mma16816(oacc[db * 2 + 1], pfh, wl + 2);
                    mma16816(oacc[db * 2 + 1], pfl, wh + 2);
                }
            }
        }
        // no trailing barrier: next iteration's top barrier covers reuse
    }

    {
        lp[0] += __shfl_xor_sync(0xffffffffu, lp[0], 1);
        lp[0] += __shfl_xor_sync(0xffffffffu, lp[0], 2);
        lp[1] += __shfl_xor_sync(0xffffffffu, lp[1], 1);
        lp[1] += __shfl_xor_sync(0xffffffffu, lp[1], 2);
        float* reds = (float*)(sm + ARED_OFF);
        __syncthreads();                      // all PV reads done before smem reuse below
        if ((lane & 3) == 0) {
            reds[wn * 128 + row1] = lp[0];
            reds[wn * 128 + row2] = lp[1];
        }
        float* ox = (float*)sm;
        if (wn == 1) {
            #pragma unroll
            for (int nt = 0; nt < 16; nt++) {
                int c0 = nt * 8 + (lane & 3) * 2;
                *(float2*)(ox + (size_t)row1 * 128 + c0) = make_float2(oacc[nt][0], oacc[nt][1]);
                *(float2*)(ox + (size_t)row2 * 128 + c0) = make_float2(oacc[nt][2], oacc[nt][3]);
            }
        }
        __syncthreads();
        if (wn == 0) {
            float inv1 = 1.f / (reds[row1] + reds[128 + row1]);
            float inv2 = 1.f / (reds[row2] + reds[128 + row2]);
            int rg1 = qt * 128 + row1, rg2 = qt * 128 + row2;
            size_t b1 = ((size_t)(b * SEQ + rg1) * NH + h) * HD;
            size_t b2 = ((size_t)(b * SEQ + rg2) * NH + h) * HD;
            #pragma unroll
            for (int nt = 0; nt < 16; nt++) {
                int c0 = nt * 8 + (lane & 3) * 2;
                float2 x1 = *(float2*)(ox + (size_t)row1 * 128 + c0);
                float2 x2 = *(float2*)(ox + (size_t)row2 * 128 + c0);
                float f0 = (oacc[nt][0] + x1.x) * inv1;
                float f1 = (oacc[nt][1] + x1.y) * inv1;
                float f2 = (oacc[nt][2] + x2.x) * inv2;
                float f3 = (oacc[nt][3] + x2.y) * inv2;
                uint32_t h01 = packbf(f0, f1), h23 = packbf(f2, f3);
                __nv_bfloat162 bb01 = *(__nv_bfloat162*)&h01;
                __nv_bfloat162 bb23 = *(__nv_bfloat162*)&h23;
                uint32_t l01 = packbf(f0 - __bfloat162float(bb01.x), f1 - __bfloat162float(bb01.y));
                uint32_t l23 = packbf(f2 - __bfloat162float(bb23.x), f3 - __bfloat162float(bb23.y));
                *(uint32_t*)(outh + b1 + c0) = h01;
                *(uint32_t*)(outh + b2 + c0) = h23;
                *(uint32_t*)(outl + b1 + c0) = l01;
                *(uint32_t*)(outl + b2 + c0) = l23;
            }
        }
    }
#undef LOAD_KV
}

// ============================================================
// launch  (R16 structure)
// ============================================================
extern "C" void kernel_launch(void* const* d_in, const int* in_sizes, int n_in,
                              void* d_out, int out_size)
{
    const float* x  = (const float*)d_in[0];
    const float* wq = (const float*)d_in[1];
    const float* wk = (const float*)d_in[2];
    const float* wv = (const float*)d_in[3];
    const float* wo = (const float*)d_in[4];
    const float* fcos = (const float*)d_in[7];
    const float* fsin = (const float*)d_in[8];
    float* out = (float*)d_out;

    float* gqkv;
    __nv_bfloat16 *xh, *xl, *wqkvTh, *wqkvTl, *woTh, *woTl;
    __nv_bfloat16 *aoh, *aol, *pqh, *pql, *pkh, *pkl, *pvh, *pvl;
    cudaGetSymbolAddress((void**)&gqkv, g_qkv);
    cudaGetSymbolAddress((void**)&xh, g_xh);         cudaGetSymbolAddress((void**)&xl, g_xl);
    cudaGetSymbolAddress((void**)&wqkvTh, g_wqkvTh); cudaGetSymbolAddress((void**)&wqkvTl, g_wqkvTl);
    cudaGetSymbolAddress((void**)&woTh, g_woTh);     cudaGetSymbolAddress((void**)&woTl, g_woTl);
    cudaGetSymbolAddress((void**)&aoh, g_aoh);       cudaGetSymbolAddress((void**)&aol, g_aol);
    cudaGetSymbolAddress((void**)&pqh, g_qh);        cudaGetSymbolAddress((void**)&pql, g_ql);
    cudaGetSymbolAddress((void**)&pkh, g_kh);        cudaGetSymbolAddress((void**)&pkl, g_kl);
    cudaGetSymbolAddress((void**)&pvh, g_vh);        cudaGetSymbolAddress((void**)&pvl, g_vl);

    cudaFuncSetAttribute(gemm_mma, cudaFuncAttributeMaxDynamicSharedMemorySize, GEMM_SMEM);
    cudaFuncSetAttribute(attn_mma, cudaFuncAttributeMaxDynamicSharedMemorySize, ATT_SMEM);

    // 0: prep
    prep_kernel<<<PREP_TOTAL, 256>>>(x, wq, wk, wv, wo, xh, xl, wqkvTh, wqkvTl, woTh, woTl);
    // 1: fused qkv projection
    gemm_mma<<<dim3(NQKV / BN, MTOT / BM), 512, GEMM_SMEM>>>(xh, xl, wqkvTh, wqkvTl,
                                                             gqkv, MTOT, NQKV, DIM);
    // 2: rope + split + relayout (float4 per thread)
    {
        int total = BATCH * SEQ * (NH + 2 * NKV) * (HD / 4);
        rope_split<<<(total + 255) / 256, 256>>>(gqkv, fcos, fsin,
                                                 pqh, pql, pkh, pkl, pvh, pvl);
    }
    // 3: attention  <-- ncu capture slot
    {
        dim3 grid(SEQ / 128, NH, BATCH);
        attn_mma<<<grid, 512, ATT_SMEM>>>(pqh, pql, pkh, pkl, pvh, pvl, aoh, aol);
    }
    // 4: output projection
    gemm_mma<<<dim3(DIM / BN, MTOT / BM), 512, GEMM_SMEM>>>(aoh, aol, woTh, woTl, out, MTOT, DIM, NQ);
}